// round 1
// baseline (speedup 1.0000x reference)
#include <cuda_runtime.h>
#include <math.h>

// Problem constants
#define BATCH 2
#define TDIM 2048
#define CDIM 1024
#define HN 16
#define HD 64
#define BT (BATCH * TDIM)        // 4096 rows
#define BH (BATCH * HN)          // 32 batch-heads
#define QKVC (3 * CDIM)          // 3072
#define FFC (4 * CDIM)           // 4096

// -------- scratch (static device globals; no allocation) ----------
__device__ float g_h[BT * CDIM];        // layernorm output (reused ln1/ln2)
__device__ float g_qkv[BT * QKVC];      // qkv projection
__device__ float g_y[BT * CDIM];        // attention output (pre-proj)
__device__ float g_x1[BT * CDIM];       // x + attn branch
__device__ float g_m[BT * FFC];         // gelu(fc) activations
__device__ float g_ent;                 // entropy accumulator

// ------------------------------------------------------------------
__global__ void zero_ent_kernel() { g_ent = 0.0f; }

__global__ void finalize_kernel(float* out, int out_size) {
    if (out_size > BT * CDIM)
        out[BT * CDIM] = g_ent * (1.0f / (float)(BH * TDIM));
}

// -------- LayerNorm: one block per row, 256 threads ---------------
__global__ void ln_kernel(const float* __restrict__ x,
                          const float* __restrict__ w,
                          const float* __restrict__ b,
                          float* __restrict__ out) {
    int row = blockIdx.x;
    int tid = threadIdx.x;
    const float* xr = x + (size_t)row * CDIM;
    __shared__ float red[256];

    float v[4];
    float lsum = 0.f, lsq = 0.f;
#pragma unroll
    for (int i = 0; i < 4; i++) {
        v[i] = xr[tid + i * 256];
        lsum += v[i];
        lsq  += v[i] * v[i];
    }
    red[tid] = lsum; __syncthreads();
    for (int s = 128; s > 0; s >>= 1) {
        if (tid < s) red[tid] += red[tid + s];
        __syncthreads();
    }
    float mean = red[0] * (1.0f / CDIM);
    __syncthreads();
    red[tid] = lsq; __syncthreads();
    for (int s = 128; s > 0; s >>= 1) {
        if (tid < s) red[tid] += red[tid + s];
        __syncthreads();
    }
    float var = red[0] * (1.0f / CDIM) - mean * mean;
    float rstd = rsqrtf(var + 1e-5f);
#pragma unroll
    for (int i = 0; i < 4; i++) {
        int c = tid + i * 256;
        out[(size_t)row * CDIM + c] = (v[i] - mean) * rstd * w[c] + b[c];
    }
}

// -------- GEMM: C[M,N] = A[M,K] * W[N,K]^T + bias (+gelu/+resid) --
// 64x64 block tile, BK=16, 256 threads, 4x4 microtile per thread.
__device__ __forceinline__ float gelu_tanh(float x) {
    const float k0 = 0.7978845608028654f;   // sqrt(2/pi)
    const float k1 = 0.044715f;
    float x3 = x * x * x;
    return 0.5f * x * (1.0f + tanhf(k0 * (x + k1 * x3)));
}

__global__ void gemm_kernel(const float* __restrict__ A,
                            const float* __restrict__ W,
                            const float* __restrict__ bias,
                            const float* __restrict__ resid,
                            float* __restrict__ C,
                            int M, int N, int K, int act) {
    __shared__ float As[64][17];
    __shared__ float Ws[64][17];
    int tid = threadIdx.x;
    int tx = tid & 15;        // 0..15
    int ty = tid >> 4;        // 0..15
    int rowBase = blockIdx.y * 64;
    int colBase = blockIdx.x * 64;

    float acc[4][4] = {};

    for (int kt = 0; kt < K; kt += 16) {
#pragma unroll
        for (int i = 0; i < 4; i++) {
            int idx = tid + i * 256;
            int r = idx >> 4;
            int c = idx & 15;
            As[r][c] = A[(size_t)(rowBase + r) * K + kt + c];
            Ws[r][c] = W[(size_t)(colBase + r) * K + kt + c];
        }
        __syncthreads();
#pragma unroll
        for (int k = 0; k < 16; k++) {
            float a[4], bv[4];
#pragma unroll
            for (int i = 0; i < 4; i++) a[i] = As[ty * 4 + i][k];
#pragma unroll
            for (int j = 0; j < 4; j++) bv[j] = Ws[tx * 4 + j][k];
#pragma unroll
            for (int i = 0; i < 4; i++)
#pragma unroll
                for (int j = 0; j < 4; j++)
                    acc[i][j] += a[i] * bv[j];
        }
        __syncthreads();
    }

#pragma unroll
    for (int i = 0; i < 4; i++) {
        int r = rowBase + ty * 4 + i;
#pragma unroll
        for (int j = 0; j < 4; j++) {
            int c = colBase + tx * 4 + j;
            float v = acc[i][j] + bias[c];
            if (act == 1) v = gelu_tanh(v);
            if (resid) v += resid[(size_t)r * N + c];
            C[(size_t)r * N + c] = v;
        }
    }
}

// -------- Attention: one block per (bh, q) ------------------------
// qkv layout: row = b*T + t, cols [0,1024)=Q [1024,2048)=K [2048,3072)=V
// head h owns cols h*64..h*64+63 within each third.
__global__ void attn_kernel(const float* __restrict__ qkv,
                            float* __restrict__ y) {
    int q  = blockIdx.x;
    int bh = blockIdx.y;
    int b  = bh >> 4;
    int h  = bh & 15;
    int tid = threadIdx.x;

    __shared__ float q_s[64];
    __shared__ float sc[TDIM];        // scores / probs for this row
    __shared__ float kv[128][65];     // K or V chunk (padded)
    __shared__ float red[128];

    const float* base = qkv + (size_t)b * TDIM * QKVC + h * HD;
    if (tid < 64) q_s[tid] = base[(size_t)q * QKVC + tid];
    int nk = q + 1;
    __syncthreads();

    // ---- scores: s[k] = (q . k) / sqrt(64) ----
    for (int k0 = 0; k0 < nk; k0 += 128) {
        int cnt = min(128, nk - k0);
        for (int idx = tid; idx < cnt * 64; idx += 128) {
            int kk = idx >> 6, d = idx & 63;
            kv[kk][d] = base[(size_t)(k0 + kk) * QKVC + CDIM + d];
        }
        __syncthreads();
        if (tid < cnt) {
            float s = 0.f;
#pragma unroll
            for (int d = 0; d < 64; d++) s += q_s[d] * kv[tid][d];
            sc[k0 + tid] = s * 0.125f;   // 1/sqrt(64)
        }
        __syncthreads();
    }

    // ---- softmax max ----
    float lm = -INFINITY;
    for (int k = tid; k < nk; k += 128) lm = fmaxf(lm, sc[k]);
    red[tid] = lm; __syncthreads();
    for (int s = 64; s > 0; s >>= 1) {
        if (tid < s) red[tid] = fmaxf(red[tid], red[tid + s]);
        __syncthreads();
    }
    float mx = red[0]; __syncthreads();

    // ---- exp + sum ----
    float ls = 0.f;
    for (int k = tid; k < nk; k += 128) {
        float e = __expf(sc[k] - mx);
        sc[k] = e;
        ls += e;
    }
    red[tid] = ls; __syncthreads();
    for (int s = 64; s > 0; s >>= 1) {
        if (tid < s) red[tid] += red[tid + s];
        __syncthreads();
    }
    float S = red[0]; __syncthreads();
    float inv = 1.0f / S;

    // ---- normalize + entropy ----
    float lent = 0.f;
    for (int k = tid; k < nk; k += 128) {
        float p = sc[k] * inv;
        sc[k] = p;
        lent -= p * __logf(p + 1e-8f);
    }
    red[tid] = lent; __syncthreads();
    for (int s = 64; s > 0; s >>= 1) {
        if (tid < s) red[tid] += red[tid + s];
        __syncthreads();
    }
    if (tid == 0) atomicAdd(&g_ent, red[0]);
    __syncthreads();

    // ---- out = P . V  (threads 0..63 -> half 0, 64..127 -> half 1) ----
    int d = tid & 63;
    int half = tid >> 6;
    float acc = 0.f;
    for (int k0 = 0; k0 < nk; k0 += 128) {
        int cnt = min(128, nk - k0);
        for (int idx = tid; idx < cnt * 64; idx += 128) {
            int kk = idx >> 6, dd = idx & 63;
            kv[kk][dd] = base[(size_t)(k0 + kk) * QKVC + 2 * CDIM + dd];
        }
        __syncthreads();
        int jb = half * 64;
        int je = min(cnt, jb + 64);
        for (int j = jb; j < je; j++) acc += sc[k0 + j] * kv[j][d];
        __syncthreads();
    }
    red[tid] = acc; __syncthreads();
    if (tid < 64) {
        float o = red[tid] + red[tid + 64];
        y[(size_t)(b * TDIM + q) * CDIM + h * HD + tid] = o;
    }
}

// ------------------------------------------------------------------
extern "C" void kernel_launch(void* const* d_in, const int* in_sizes, int n_in,
                              void* d_out, int out_size) {
    const float* x          = (const float*)d_in[0];
    const float* ln1_w      = (const float*)d_in[1];
    const float* ln1_b      = (const float*)d_in[2];
    const float* attn_w     = (const float*)d_in[3];
    const float* attn_b     = (const float*)d_in[4];
    const float* attnproj_w = (const float*)d_in[5];
    const float* attnproj_b = (const float*)d_in[6];
    const float* ln2_w      = (const float*)d_in[7];
    const float* ln2_b      = (const float*)d_in[8];
    const float* fc_w       = (const float*)d_in[9];
    const float* fc_b       = (const float*)d_in[10];
    const float* proj_w     = (const float*)d_in[11];
    const float* proj_b     = (const float*)d_in[12];
    float* out = (float*)d_out;

    float *p_h, *p_qkv, *p_y, *p_x1, *p_m;
    cudaGetSymbolAddress((void**)&p_h,   g_h);
    cudaGetSymbolAddress((void**)&p_qkv, g_qkv);
    cudaGetSymbolAddress((void**)&p_y,   g_y);
    cudaGetSymbolAddress((void**)&p_x1,  g_x1);
    cudaGetSymbolAddress((void**)&p_m,   g_m);

    zero_ent_kernel<<<1, 1>>>();

    // h = LN1(x)
    ln_kernel<<<BT, 256>>>(x, ln1_w, ln1_b, p_h);

    // qkv = h @ attn_w^T + attn_b        [4096, 3072]
    gemm_kernel<<<dim3(QKVC / 64, BT / 64), 256>>>(
        p_h, attn_w, attn_b, nullptr, p_qkv, BT, QKVC, CDIM, 0);

    // attention (+entropy)
    attn_kernel<<<dim3(TDIM, BH), 128>>>(p_qkv, p_y);

    // x1 = x + y @ attnproj_w^T + attnproj_b
    gemm_kernel<<<dim3(CDIM / 64, BT / 64), 256>>>(
        p_y, attnproj_w, attnproj_b, x, p_x1, BT, CDIM, CDIM, 0);

    // h = LN2(x1)
    ln_kernel<<<BT, 256>>>(p_x1, ln2_w, ln2_b, p_h);

    // m = gelu(h @ fc_w^T + fc_b)        [4096, 4096]
    gemm_kernel<<<dim3(FFC / 64, BT / 64), 256>>>(
        p_h, fc_w, fc_b, nullptr, p_m, BT, FFC, CDIM, 1);

    // out = x1 + m @ proj_w^T + proj_b   -> directly into d_out
    gemm_kernel<<<dim3(CDIM / 64, BT / 64), 256>>>(
        p_m, proj_w, proj_b, p_x1, out, BT, CDIM, FFC, 0);

    // entropy scalar
    finalize_kernel<<<1, 1>>>(out, out_size);
}

// round 2
// speedup vs baseline: 3.5249x; 3.5249x over previous
#include <cuda_runtime.h>
#include <math.h>

// Problem constants
#define BATCH 2
#define TDIM 2048
#define CDIM 1024
#define HN 16
#define HD 64
#define BT (BATCH * TDIM)        // 4096 rows
#define BH (BATCH * HN)          // 32 batch-heads
#define QKVC (3 * CDIM)          // 3072
#define FFC (4 * CDIM)           // 4096

#define NEG_BIG (-1e30f)

// -------- scratch (static device globals; no allocation) ----------
__device__ float g_h[BT * CDIM];        // layernorm output (reused ln1/ln2)
__device__ float g_qkv[BT * QKVC];      // qkv projection
__device__ float g_y[BT * CDIM];        // attention output (pre-proj)
__device__ float g_x1[BT * CDIM];       // x + attn branch
__device__ float g_m[BT * FFC];         // gelu(fc) activations
__device__ float g_ent;                 // entropy accumulator

// ------------------------------------------------------------------
__global__ void zero_ent_kernel() { g_ent = 0.0f; }

__global__ void finalize_kernel(float* out, int out_size) {
    if (out_size > BT * CDIM)
        out[BT * CDIM] = g_ent * (1.0f / (float)(BH * TDIM));
}

// -------- LayerNorm: one block per row, 256 threads ---------------
__global__ void ln_kernel(const float* __restrict__ x,
                          const float* __restrict__ w,
                          const float* __restrict__ b,
                          float* __restrict__ out) {
    int row = blockIdx.x;
    int tid = threadIdx.x;
    const float* xr = x + (size_t)row * CDIM;
    __shared__ float red[256];

    float v[4];
    float lsum = 0.f, lsq = 0.f;
#pragma unroll
    for (int i = 0; i < 4; i++) {
        v[i] = xr[tid + i * 256];
        lsum += v[i];
        lsq  += v[i] * v[i];
    }
    red[tid] = lsum; __syncthreads();
    for (int s = 128; s > 0; s >>= 1) {
        if (tid < s) red[tid] += red[tid + s];
        __syncthreads();
    }
    float mean = red[0] * (1.0f / CDIM);
    __syncthreads();
    red[tid] = lsq; __syncthreads();
    for (int s = 128; s > 0; s >>= 1) {
        if (tid < s) red[tid] += red[tid + s];
        __syncthreads();
    }
    float var = red[0] * (1.0f / CDIM) - mean * mean;
    float rstd = rsqrtf(var + 1e-5f);
#pragma unroll
    for (int i = 0; i < 4; i++) {
        int c = tid + i * 256;
        out[(size_t)row * CDIM + c] = (v[i] - mean) * rstd * w[c] + b[c];
    }
}

// -------- packed f32x2 helpers ------------------------------------
__device__ __forceinline__ unsigned long long pack2(float x, float y) {
    unsigned long long r;
    asm("mov.b64 %0, {%1, %2};" : "=l"(r) : "f"(x), "f"(y));
    return r;
}
__device__ __forceinline__ void unpack2(unsigned long long v, float& x, float& y) {
    asm("mov.b64 {%0, %1}, %2;" : "=f"(x), "=f"(y) : "l"(v));
}
__device__ __forceinline__ void ffma2(unsigned long long& d,
                                      unsigned long long a,
                                      unsigned long long b) {
    asm("fma.rn.f32x2 %0, %1, %2, %0;" : "+l"(d) : "l"(a), "l"(b));
}

__device__ __forceinline__ float gelu_tanh(float x) {
    const float k0 = 0.7978845608028654f;   // sqrt(2/pi)
    const float k1 = 0.044715f;
    float x3 = x * x * x;
    return 0.5f * x * (1.0f + tanhf(k0 * (x + k1 * x3)));
}

// -------- GEMM: C[M,N] = A[M,K] * W[N,K]^T + bias (+gelu/+resid) --
// 128x128 block tile, BK=16, 256 threads, 8x8 microtile, f32x2 FMA.
__global__ __launch_bounds__(256)
void gemm_kernel(const float* __restrict__ A,
                 const float* __restrict__ W,
                 const float* __restrict__ bias,
                 const float* __restrict__ resid,
                 float* __restrict__ C,
                 int M, int N, int K, int act) {
    __shared__ float As[16][132];   // [k][m]
    __shared__ float Ws[16][132];   // [k][n]
    int tid = threadIdx.x;
    int tx = tid & 15;
    int ty = tid >> 4;
    int rowBase = blockIdx.y * 128;
    int colBase = blockIdx.x * 128;

    const float* Aptr = A + (size_t)rowBase * K;
    const float* Wptr = W + (size_t)colBase * K;

    float4 pa[2], pw[2];

    unsigned long long acc[8][4];
#pragma unroll
    for (int i = 0; i < 8; i++)
#pragma unroll
        for (int p = 0; p < 4; p++) acc[i][p] = 0ull;

    // --- load first tile into regs ---
#pragma unroll
    for (int it = 0; it < 2; it++) {
        int li = tid + it * 256;
        int r = li >> 2, c4 = li & 3;
        pa[it] = *(const float4*)&Aptr[(size_t)r * K + c4 * 4];
        pw[it] = *(const float4*)&Wptr[(size_t)r * K + c4 * 4];
    }
#pragma unroll
    for (int it = 0; it < 2; it++) {
        int li = tid + it * 256;
        int r = li >> 2, c4 = li & 3;
        As[c4 * 4 + 0][r] = pa[it].x; As[c4 * 4 + 1][r] = pa[it].y;
        As[c4 * 4 + 2][r] = pa[it].z; As[c4 * 4 + 3][r] = pa[it].w;
        Ws[c4 * 4 + 0][r] = pw[it].x; Ws[c4 * 4 + 1][r] = pw[it].y;
        Ws[c4 * 4 + 2][r] = pw[it].z; Ws[c4 * 4 + 3][r] = pw[it].w;
    }
    __syncthreads();

    int nt = K >> 4;
    for (int t = 1; t <= nt; t++) {
        if (t < nt) {
            int kt = t << 4;
#pragma unroll
            for (int it = 0; it < 2; it++) {
                int li = tid + it * 256;
                int r = li >> 2, c4 = li & 3;
                pa[it] = *(const float4*)&Aptr[(size_t)r * K + kt + c4 * 4];
                pw[it] = *(const float4*)&Wptr[(size_t)r * K + kt + c4 * 4];
            }
        }
        // compute on current smem tile
#pragma unroll
        for (int k = 0; k < 16; k++) {
            float4 a0 = *(float4*)&As[k][ty * 4];
            float4 a1 = *(float4*)&As[k][64 + ty * 4];
            float4 b0 = *(float4*)&Ws[k][tx * 4];
            float4 b1 = *(float4*)&Ws[k][64 + tx * 4];
            unsigned long long bp[4];
            bp[0] = pack2(b0.x, b0.y); bp[1] = pack2(b0.z, b0.w);
            bp[2] = pack2(b1.x, b1.y); bp[3] = pack2(b1.z, b1.w);
            float av[8] = {a0.x, a0.y, a0.z, a0.w, a1.x, a1.y, a1.z, a1.w};
#pragma unroll
            for (int i = 0; i < 8; i++) {
                unsigned long long ap = pack2(av[i], av[i]);
#pragma unroll
                for (int p = 0; p < 4; p++) ffma2(acc[i][p], ap, bp[p]);
            }
        }
        if (t < nt) {
            __syncthreads();
#pragma unroll
            for (int it = 0; it < 2; it++) {
                int li = tid + it * 256;
                int r = li >> 2, c4 = li & 3;
                As[c4 * 4 + 0][r] = pa[it].x; As[c4 * 4 + 1][r] = pa[it].y;
                As[c4 * 4 + 2][r] = pa[it].z; As[c4 * 4 + 3][r] = pa[it].w;
                Ws[c4 * 4 + 0][r] = pw[it].x; Ws[c4 * 4 + 1][r] = pw[it].y;
                Ws[c4 * 4 + 2][r] = pw[it].z; Ws[c4 * 4 + 3][r] = pw[it].w;
            }
            __syncthreads();
        }
    }

    // epilogue
#pragma unroll
    for (int i = 0; i < 8; i++) {
        int r = rowBase + ((i < 4) ? (ty * 4 + i) : (64 + ty * 4 + i - 4));
        float* crow = C + (size_t)r * N;
        const float* rrow = resid ? resid + (size_t)r * N : nullptr;
        float v[8];
        unpack2(acc[i][0], v[0], v[1]); unpack2(acc[i][1], v[2], v[3]);
        unpack2(acc[i][2], v[4], v[5]); unpack2(acc[i][3], v[6], v[7]);
#pragma unroll
        for (int j = 0; j < 8; j++) {
            int c = colBase + ((j < 4) ? (tx * 4 + j) : (64 + tx * 4 + j - 4));
            float val = v[j] + bias[c];
            if (act == 1) val = gelu_tanh(val);
            if (rrow) val += rrow[c];
            crow[c] = val;
        }
    }
}

// -------- Flash attention: 64q x 64k tiles, online softmax + entropy
// grid: (T/64, BH), 256 threads. dynamic smem.
__global__ __launch_bounds__(256)
void flash_attn_kernel(const float* __restrict__ qkv, float* __restrict__ y) {
    extern __shared__ float sm[];
    float* Qt   = sm;                 // [d][q] 64*68
    float* Kt   = Qt + 64 * 68;       // [d][k] 64*68
    float* Vs   = Kt + 64 * 68;       // [k][d] 64*64
    float* Ps   = Vs + 64 * 64;       // [q][k] 64*64
    float* mrow = Ps + 64 * 64;       // 64
    float* lrow = mrow + 64;          // 64
    float* wrow = lrow + 64;          // 64
    float* cf   = wrow + 64;          // 64

    int tid = threadIdx.x;
    int tx = tid & 15, ty = tid >> 4;
    int qt = blockIdx.x;
    int bh = blockIdx.y;
    int b = bh >> 4, h = bh & 15;
    int qb = qt * 64;
    const float* base = qkv + (size_t)b * TDIM * QKVC + h * HD;

    // load Q tile transposed
#pragma unroll
    for (int it = 0; it < 4; it++) {
        int idx = tid + it * 256;
        int qq = idx >> 4, c4 = idx & 15;
        float4 v = *(const float4*)&base[(size_t)(qb + qq) * QKVC + c4 * 4];
        Qt[(c4 * 4 + 0) * 68 + qq] = v.x;
        Qt[(c4 * 4 + 1) * 68 + qq] = v.y;
        Qt[(c4 * 4 + 2) * 68 + qq] = v.z;
        Qt[(c4 * 4 + 3) * 68 + qq] = v.w;
    }
    if (tid < 64) { mrow[tid] = NEG_BIG; lrow[tid] = 0.f; wrow[tid] = 0.f; }

    float oacc[4][4] = {};
    __syncthreads();

    for (int kb = 0; kb <= qb; kb += 64) {
        // load K (transposed) and V (natural)
#pragma unroll
        for (int it = 0; it < 4; it++) {
            int idx = tid + it * 256;
            int kk = idx >> 4, c4 = idx & 15;
            const float* rp = &base[(size_t)(kb + kk) * QKVC];
            float4 kv4 = *(const float4*)&rp[CDIM + c4 * 4];
            Kt[(c4 * 4 + 0) * 68 + kk] = kv4.x;
            Kt[(c4 * 4 + 1) * 68 + kk] = kv4.y;
            Kt[(c4 * 4 + 2) * 68 + kk] = kv4.z;
            Kt[(c4 * 4 + 3) * 68 + kk] = kv4.w;
            float4 vv4 = *(const float4*)&rp[2 * CDIM + c4 * 4];
            *(float4*)&Vs[kk * 64 + c4 * 4] = vv4;
        }
        __syncthreads();

        // scores S[q][k]
        float sacc[4][4] = {};
#pragma unroll
        for (int d = 0; d < 64; d++) {
            float4 a = *(float4*)&Qt[d * 68 + ty * 4];
            float4 bb = *(float4*)&Kt[d * 68 + tx * 4];
            float aa[4] = {a.x, a.y, a.z, a.w};
            float bv[4] = {bb.x, bb.y, bb.z, bb.w};
#pragma unroll
            for (int i = 0; i < 4; i++)
#pragma unroll
                for (int j = 0; j < 4; j++)
                    sacc[i][j] += aa[i] * bv[j];
        }
        bool diag = (kb == qb);
#pragma unroll
        for (int i = 0; i < 4; i++) {
#pragma unroll
            for (int j = 0; j < 4; j++) {
                float s = sacc[i][j] * 0.125f;
                if (diag && (tx * 4 + j) > (ty * 4 + i)) s = NEG_BIG;
                Ps[(ty * 4 + i) * 64 + tx * 4 + j] = s;
            }
        }
        __syncthreads();

        // online softmax update: 8 warps x 8 rows
        {
            int wid = tid >> 5, lane = tid & 31;
#pragma unroll
            for (int r = 0; r < 8; r++) {
                int q = wid * 8 + r;
                float s0 = Ps[q * 64 + lane];
                float s1 = Ps[q * 64 + 32 + lane];
                float tmx = fmaxf(s0, s1);
#pragma unroll
                for (int o = 16; o > 0; o >>= 1)
                    tmx = fmaxf(tmx, __shfl_xor_sync(0xFFFFFFFFu, tmx, o));
                float mold = mrow[q];
                float mnew = fmaxf(mold, tmx);
                float e0 = __expf(s0 - mnew);
                float e1 = __expf(s1 - mnew);
                float se = e0 + e1;
                float sw = e0 * s0 + e1 * s1;
#pragma unroll
                for (int o = 16; o > 0; o >>= 1) {
                    se += __shfl_xor_sync(0xFFFFFFFFu, se, o);
                    sw += __shfl_xor_sync(0xFFFFFFFFu, sw, o);
                }
                float c = __expf(mold - mnew);
                if (lane == 0) {
                    mrow[q] = mnew;
                    lrow[q] = lrow[q] * c + se;
                    wrow[q] = wrow[q] * c + sw;
                    cf[q] = c;
                }
                Ps[q * 64 + lane] = e0;
                Ps[q * 64 + 32 + lane] = e1;
            }
        }
        __syncthreads();

        // O = O * c + P~ . V
        float c0[4];
#pragma unroll
        for (int i = 0; i < 4; i++) c0[i] = cf[ty * 4 + i];
#pragma unroll
        for (int i = 0; i < 4; i++)
#pragma unroll
            for (int j = 0; j < 4; j++) oacc[i][j] *= c0[i];
#pragma unroll
        for (int k = 0; k < 64; k++) {
            float a0 = Ps[(ty * 4 + 0) * 64 + k];
            float a1 = Ps[(ty * 4 + 1) * 64 + k];
            float a2 = Ps[(ty * 4 + 2) * 64 + k];
            float a3 = Ps[(ty * 4 + 3) * 64 + k];
            float4 bv = *(float4*)&Vs[k * 64 + tx * 4];
            float bb[4] = {bv.x, bv.y, bv.z, bv.w};
#pragma unroll
            for (int j = 0; j < 4; j++) {
                oacc[0][j] += a0 * bb[j];
                oacc[1][j] += a1 * bb[j];
                oacc[2][j] += a2 * bb[j];
                oacc[3][j] += a3 * bb[j];
            }
        }
        __syncthreads();
    }

    // write O / l
#pragma unroll
    for (int i = 0; i < 4; i++) {
        int q = qb + ty * 4 + i;
        float linv = 1.0f / lrow[ty * 4 + i];
        float4 o;
        o.x = oacc[i][0] * linv; o.y = oacc[i][1] * linv;
        o.z = oacc[i][2] * linv; o.w = oacc[i][3] * linv;
        *(float4*)&y[(size_t)(b * TDIM + q) * CDIM + h * HD + tx * 4] = o;
    }

    // entropy: H_row = m + log(S) - W/S
    if (tid < 64) {
        float S = lrow[tid];
        Ps[tid] = mrow[tid] + logf(S) - wrow[tid] / S;
    }
    __syncthreads();
    if (tid == 0) {
        float tot = 0.f;
        for (int i = 0; i < 64; i++) tot += Ps[i];
        atomicAdd(&g_ent, tot);
    }
}

// ------------------------------------------------------------------
extern "C" void kernel_launch(void* const* d_in, const int* in_sizes, int n_in,
                              void* d_out, int out_size) {
    const float* x          = (const float*)d_in[0];
    const float* ln1_w      = (const float*)d_in[1];
    const float* ln1_b      = (const float*)d_in[2];
    const float* attn_w     = (const float*)d_in[3];
    const float* attn_b     = (const float*)d_in[4];
    const float* attnproj_w = (const float*)d_in[5];
    const float* attnproj_b = (const float*)d_in[6];
    const float* ln2_w      = (const float*)d_in[7];
    const float* ln2_b      = (const float*)d_in[8];
    const float* fc_w       = (const float*)d_in[9];
    const float* fc_b       = (const float*)d_in[10];
    const float* proj_w     = (const float*)d_in[11];
    const float* proj_b     = (const float*)d_in[12];
    float* out = (float*)d_out;

    float *p_h, *p_qkv, *p_y, *p_x1, *p_m;
    cudaGetSymbolAddress((void**)&p_h,   g_h);
    cudaGetSymbolAddress((void**)&p_qkv, g_qkv);
    cudaGetSymbolAddress((void**)&p_y,   g_y);
    cudaGetSymbolAddress((void**)&p_x1,  g_x1);
    cudaGetSymbolAddress((void**)&p_m,   g_m);

    // flash attention dynamic smem
    static int attn_smem = (64 * 68 * 2 + 64 * 64 * 2 + 4 * 64) * 4;
    cudaFuncSetAttribute(flash_attn_kernel,
                         cudaFuncAttributeMaxDynamicSharedMemorySize, attn_smem);

    zero_ent_kernel<<<1, 1>>>();

    // h = LN1(x)
    ln_kernel<<<BT, 256>>>(x, ln1_w, ln1_b, p_h);

    // qkv = h @ attn_w^T + attn_b        [4096, 3072]
    gemm_kernel<<<dim3(QKVC / 128, BT / 128), 256>>>(
        p_h, attn_w, attn_b, nullptr, p_qkv, BT, QKVC, CDIM, 0);

    // attention (+entropy)
    flash_attn_kernel<<<dim3(TDIM / 64, BH), 256, attn_smem>>>(p_qkv, p_y);

    // x1 = x + y @ attnproj_w^T + attnproj_b
    gemm_kernel<<<dim3(CDIM / 128, BT / 128), 256>>>(
        p_y, attnproj_w, attnproj_b, x, p_x1, BT, CDIM, CDIM, 0);

    // h = LN2(x1)
    ln_kernel<<<BT, 256>>>(p_x1, ln2_w, ln2_b, p_h);

    // m = gelu(h @ fc_w^T + fc_b)        [4096, 4096]
    gemm_kernel<<<dim3(FFC / 128, BT / 128), 256>>>(
        p_h, fc_w, fc_b, nullptr, p_m, BT, FFC, CDIM, 1);

    // out = x1 + m @ proj_w^T + proj_b   -> directly into d_out
    gemm_kernel<<<dim3(CDIM / 128, BT / 128), 256>>>(
        p_m, proj_w, proj_b, p_x1, out, BT, CDIM, FFC, 0);

    // entropy scalar
    finalize_kernel<<<1, 1>>>(out, out_size);
}

// round 3
// speedup vs baseline: 8.0007x; 2.2698x over previous
#include <cuda_runtime.h>
#include <math.h>

// Problem constants
#define BATCH 2
#define TDIM 2048
#define CDIM 1024
#define HN 16
#define HD 64
#define BT (BATCH * TDIM)        // 4096 rows
#define BH (BATCH * HN)          // 32 batch-heads
#define QKVC (3 * CDIM)          // 3072
#define FFC (4 * CDIM)           // 4096

#define NEG_BIG (-1e30f)

// -------- scratch (static device globals; no allocation) ----------
__device__ float g_h[BT * CDIM];
__device__ float g_qkv[BT * QKVC];
__device__ float g_y[BT * CDIM];
__device__ float g_x1[BT * CDIM];
__device__ float g_m[BT * FFC];
__device__ float g_ent;

// ------------------------------------------------------------------
__global__ void zero_ent_kernel() { g_ent = 0.0f; }

__global__ void finalize_kernel(float* out, int out_size) {
    if (out_size > BT * CDIM)
        out[BT * CDIM] = g_ent * (1.0f / (float)(BH * TDIM));
}

// -------- LayerNorm ----------------------------------------------
__global__ void ln_kernel(const float* __restrict__ x,
                          const float* __restrict__ w,
                          const float* __restrict__ b,
                          float* __restrict__ out) {
    int row = blockIdx.x;
    int tid = threadIdx.x;
    const float* xr = x + (size_t)row * CDIM;
    __shared__ float red[256];

    float v[4];
    float lsum = 0.f, lsq = 0.f;
#pragma unroll
    for (int i = 0; i < 4; i++) {
        v[i] = xr[tid + i * 256];
        lsum += v[i];
        lsq  += v[i] * v[i];
    }
    red[tid] = lsum; __syncthreads();
    for (int s = 128; s > 0; s >>= 1) {
        if (tid < s) red[tid] += red[tid + s];
        __syncthreads();
    }
    float mean = red[0] * (1.0f / CDIM);
    __syncthreads();
    red[tid] = lsq; __syncthreads();
    for (int s = 128; s > 0; s >>= 1) {
        if (tid < s) red[tid] += red[tid + s];
        __syncthreads();
    }
    float var = red[0] * (1.0f / CDIM) - mean * mean;
    float rstd = rsqrtf(var + 1e-5f);
#pragma unroll
    for (int i = 0; i < 4; i++) {
        int c = tid + i * 256;
        out[(size_t)row * CDIM + c] = (v[i] - mean) * rstd * w[c] + b[c];
    }
}

// -------- tf32 helpers -------------------------------------------
__device__ __forceinline__ unsigned f2tf(float f) {
    unsigned r;
    asm("cvt.rna.tf32.f32 %0, %1;" : "=r"(r) : "f"(f));
    return r;
}

__device__ __forceinline__ void mma_tf32(float* c, const unsigned* a, const unsigned* b) {
    asm("mma.sync.aligned.m16n8k8.row.col.f32.tf32.tf32.f32 "
        "{%0,%1,%2,%3}, {%4,%5,%6,%7}, {%8,%9}, {%0,%1,%2,%3};"
        : "+f"(c[0]), "+f"(c[1]), "+f"(c[2]), "+f"(c[3])
        : "r"(a[0]), "r"(a[1]), "r"(a[2]), "r"(a[3]), "r"(b[0]), "r"(b[1]));
}

__device__ __forceinline__ float gelu_tanh(float x) {
    const float k0 = 0.7978845608028654f;
    const float k1 = 0.044715f;
    float x3 = x * x * x;
    return 0.5f * x * (1.0f + tanhf(k0 * (x + k1 * x3)));
}

// -------- tf32 tensor-core GEMM: C = A[M,K] * W[N,K]^T + bias ------
// 128x128x32 tile, 256 threads, warp grid 2(m) x 4(n), warp tile 64x32.
__global__ __launch_bounds__(256)
void gemm_tc(const float* __restrict__ A, const float* __restrict__ W,
             const float* __restrict__ bias, const float* __restrict__ resid,
             float* __restrict__ C, int M, int N, int K, int act) {
    __shared__ unsigned As[128][36];   // stride 36: bank = 4*row+col -> conflict-free frags
    __shared__ unsigned Ws[128][36];
    int tid = threadIdx.x;
    int warp = tid >> 5, lane = tid & 31;
    int wm = warp >> 2, wn = warp & 3;
    int g = lane >> 2, tig = lane & 3;
    int rowBase = blockIdx.y * 128, colBase = blockIdx.x * 128;
    const float* Ap = A + (size_t)rowBase * K;
    const float* Wp = W + (size_t)colBase * K;

    float acc[4][4][4];
#pragma unroll
    for (int i = 0; i < 4; i++)
#pragma unroll
        for (int j = 0; j < 4; j++)
#pragma unroll
            for (int p = 0; p < 4; p++) acc[i][j][p] = 0.f;

    float4 pa[4], pw[4];
#pragma unroll
    for (int it = 0; it < 4; it++) {
        int idx = tid + it * 256;
        int r = idx >> 3, c4 = idx & 7;
        pa[it] = *(const float4*)&Ap[(size_t)r * K + c4 * 4];
        pw[it] = *(const float4*)&Wp[(size_t)r * K + c4 * 4];
    }
#pragma unroll
    for (int it = 0; it < 4; it++) {
        int idx = tid + it * 256;
        int r = idx >> 3, c = (idx & 7) * 4;
        *(uint4*)&As[r][c] = make_uint4(f2tf(pa[it].x), f2tf(pa[it].y), f2tf(pa[it].z), f2tf(pa[it].w));
        *(uint4*)&Ws[r][c] = make_uint4(f2tf(pw[it].x), f2tf(pw[it].y), f2tf(pw[it].z), f2tf(pw[it].w));
    }
    __syncthreads();

    int nt = K >> 5;
    for (int t = 1; t <= nt; t++) {
        if (t < nt) {
            int kt = t << 5;
#pragma unroll
            for (int it = 0; it < 4; it++) {
                int idx = tid + it * 256;
                int r = idx >> 3, c4 = idx & 7;
                pa[it] = *(const float4*)&Ap[(size_t)r * K + kt + c4 * 4];
                pw[it] = *(const float4*)&Wp[(size_t)r * K + kt + c4 * 4];
            }
        }
#pragma unroll
        for (int ks = 0; ks < 4; ks++) {
            unsigned af[4][4], bf[4][2];
#pragma unroll
            for (int mi = 0; mi < 4; mi++) {
                int r0 = wm * 64 + mi * 16 + g;
                af[mi][0] = As[r0][ks * 8 + tig];
                af[mi][1] = As[r0 + 8][ks * 8 + tig];
                af[mi][2] = As[r0][ks * 8 + tig + 4];
                af[mi][3] = As[r0 + 8][ks * 8 + tig + 4];
            }
#pragma unroll
            for (int nj = 0; nj < 4; nj++) {
                int c0 = wn * 32 + nj * 8 + g;
                bf[nj][0] = Ws[c0][ks * 8 + tig];
                bf[nj][1] = Ws[c0][ks * 8 + tig + 4];
            }
#pragma unroll
            for (int mi = 0; mi < 4; mi++)
#pragma unroll
                for (int nj = 0; nj < 4; nj++)
                    mma_tf32(acc[mi][nj], af[mi], bf[nj]);
        }
        if (t < nt) {
            __syncthreads();
#pragma unroll
            for (int it = 0; it < 4; it++) {
                int idx = tid + it * 256;
                int r = idx >> 3, c = (idx & 7) * 4;
                *(uint4*)&As[r][c] = make_uint4(f2tf(pa[it].x), f2tf(pa[it].y), f2tf(pa[it].z), f2tf(pa[it].w));
                *(uint4*)&Ws[r][c] = make_uint4(f2tf(pw[it].x), f2tf(pw[it].y), f2tf(pw[it].z), f2tf(pw[it].w));
            }
            __syncthreads();
        }
    }

    // epilogue: float2 stores (c regs are adjacent columns)
#pragma unroll
    for (int mi = 0; mi < 4; mi++) {
#pragma unroll
        for (int h2 = 0; h2 < 2; h2++) {
            int r = rowBase + wm * 64 + mi * 16 + g + h2 * 8;
            float* crow = C + (size_t)r * N;
            const float* rrow = resid ? resid + (size_t)r * N : nullptr;
#pragma unroll
            for (int nj = 0; nj < 4; nj++) {
                int c = colBase + wn * 32 + nj * 8 + 2 * tig;
                float v0 = acc[mi][nj][h2 * 2]     + bias[c];
                float v1 = acc[mi][nj][h2 * 2 + 1] + bias[c + 1];
                if (act == 1) { v0 = gelu_tanh(v0); v1 = gelu_tanh(v1); }
                if (rrow) { v0 += rrow[c]; v1 += rrow[c + 1]; }
                *(float2*)&crow[c] = make_float2(v0, v1);
            }
        }
    }
}

// -------- Flash attention with tf32 MMA ---------------------------
#define QS 68      // stride for Qt/Ks/Pt/Ps (bank = 4*row+col, conflict-free)
#define VS_ 72     // stride for Vs (bank = 8*row+col, conflict-free)

__global__ __launch_bounds__(256)
void flash_attn_tc(const float* __restrict__ qkv, float* __restrict__ y) {
    extern __shared__ unsigned smu[];
    unsigned* Qt = smu;                    // [64][68] tf32
    unsigned* Ks = Qt + 64 * QS;           // [64][68] tf32
    unsigned* Vs = Ks + 64 * QS;           // [64][72] tf32
    unsigned* Pt = Vs + 64 * VS_;          // [64][68] tf32 probs
    float*    Ps = (float*)(Pt + 64 * QS); // [64][68] f32 scores / scratch
    float*  mrow = Ps + 64 * QS;
    float*  lrow = mrow + 64;
    float*  wrow = lrow + 64;
    float*  cf   = wrow + 64;

    int tid = threadIdx.x;
    int warp = tid >> 5, lane = tid & 31;
    int g = lane >> 2, tig = lane & 3;
    int qt = blockIdx.x, bh = blockIdx.y;
    int b = bh >> 4, h = bh & 15;
    int qb = qt * 64;
    const float* base = qkv + (size_t)b * TDIM * QKVC + h * HD;

    int wq = warp >> 1;   // 0..3 : 16 q rows
    int wk = warp & 1;    // 0..1 : 32 cols (k for QK, d for PV)

    // load Q tile -> tf32
#pragma unroll
    for (int it = 0; it < 4; it++) {
        int idx = tid + it * 256;
        int r = idx >> 4, c = (idx & 15) * 4;
        float4 v = *(const float4*)&base[(size_t)(qb + r) * QKVC + c];
        *(uint4*)&Qt[r * QS + c] = make_uint4(f2tf(v.x), f2tf(v.y), f2tf(v.z), f2tf(v.w));
    }
    if (tid < 64) { mrow[tid] = NEG_BIG; lrow[tid] = 0.f; wrow[tid] = 0.f; }

    float oacc[4][4];
#pragma unroll
    for (int nj = 0; nj < 4; nj++)
#pragma unroll
        for (int p = 0; p < 4; p++) oacc[nj][p] = 0.f;
    __syncthreads();

    for (int kb = 0; kb <= qb; kb += 64) {
        // load K, V tiles -> tf32
#pragma unroll
        for (int it = 0; it < 4; it++) {
            int idx = tid + it * 256;
            int r = idx >> 4, c = (idx & 15) * 4;
            const float* rp = &base[(size_t)(kb + r) * QKVC];
            float4 kv = *(const float4*)&rp[CDIM + c];
            *(uint4*)&Ks[r * QS + c] = make_uint4(f2tf(kv.x), f2tf(kv.y), f2tf(kv.z), f2tf(kv.w));
            float4 vv = *(const float4*)&rp[2 * CDIM + c];
            *(uint4*)&Vs[r * VS_ + c] = make_uint4(f2tf(vv.x), f2tf(vv.y), f2tf(vv.z), f2tf(vv.w));
        }
        __syncthreads();

        // ---- S = Q K^T : warp tile 16q x 32k ----
        float sacc[4][4];
#pragma unroll
        for (int nj = 0; nj < 4; nj++)
#pragma unroll
            for (int p = 0; p < 4; p++) sacc[nj][p] = 0.f;
#pragma unroll
        for (int ks = 0; ks < 8; ks++) {
            unsigned af[4];
            int r0 = wq * 16 + g;
            af[0] = Qt[r0 * QS + ks * 8 + tig];
            af[1] = Qt[(r0 + 8) * QS + ks * 8 + tig];
            af[2] = Qt[r0 * QS + ks * 8 + tig + 4];
            af[3] = Qt[(r0 + 8) * QS + ks * 8 + tig + 4];
#pragma unroll
            for (int nj = 0; nj < 4; nj++) {
                int c0 = wk * 32 + nj * 8 + g;
                unsigned bf[2];
                bf[0] = Ks[c0 * QS + ks * 8 + tig];
                bf[1] = Ks[c0 * QS + ks * 8 + tig + 4];
                mma_tf32(sacc[nj], af, bf);
            }
        }
        bool diag = (kb == qb);
#pragma unroll
        for (int nj = 0; nj < 4; nj++) {
            int c0 = wk * 32 + nj * 8 + 2 * tig;
#pragma unroll
            for (int h2 = 0; h2 < 2; h2++) {
                int r = wq * 16 + g + h2 * 8;
                float s0 = sacc[nj][h2 * 2] * 0.125f;
                float s1 = sacc[nj][h2 * 2 + 1] * 0.125f;
                if (diag) {
                    if (c0 > r) s0 = NEG_BIG;
                    if (c0 + 1 > r) s1 = NEG_BIG;
                }
                Ps[r * QS + c0] = s0;
                Ps[r * QS + c0 + 1] = s1;
            }
        }
        __syncthreads();

        // ---- online softmax: warp handles 8 rows ----
#pragma unroll
        for (int r = 0; r < 8; r++) {
            int qq = warp * 8 + r;
            float s0 = Ps[qq * QS + lane];
            float s1 = Ps[qq * QS + 32 + lane];
            float tmx = fmaxf(s0, s1);
#pragma unroll
            for (int o = 16; o > 0; o >>= 1)
                tmx = fmaxf(tmx, __shfl_xor_sync(0xFFFFFFFFu, tmx, o));
            float mold = mrow[qq];
            float mnew = fmaxf(mold, tmx);
            float e0 = __expf(s0 - mnew);
            float e1 = __expf(s1 - mnew);
            float se = e0 + e1;
            float sw = e0 * s0 + e1 * s1;
#pragma unroll
            for (int o = 16; o > 0; o >>= 1) {
                se += __shfl_xor_sync(0xFFFFFFFFu, se, o);
                sw += __shfl_xor_sync(0xFFFFFFFFu, sw, o);
            }
            float c = __expf(mold - mnew);
            if (lane == 0) {
                mrow[qq] = mnew;
                lrow[qq] = lrow[qq] * c + se;
                wrow[qq] = wrow[qq] * c + sw;
                cf[qq] = c;
            }
            Pt[qq * QS + lane] = f2tf(e0);
            Pt[qq * QS + 32 + lane] = f2tf(e1);
        }
        __syncthreads();

        // ---- O = O*c + P V : warp tile 16q x 32d ----
        float c0f = cf[wq * 16 + g];
        float c1f = cf[wq * 16 + g + 8];
#pragma unroll
        for (int nj = 0; nj < 4; nj++) {
            oacc[nj][0] *= c0f; oacc[nj][1] *= c0f;
            oacc[nj][2] *= c1f; oacc[nj][3] *= c1f;
        }
#pragma unroll
        for (int ks = 0; ks < 8; ks++) {
            unsigned af[4];
            int r0 = wq * 16 + g;
            af[0] = Pt[r0 * QS + ks * 8 + tig];
            af[1] = Pt[(r0 + 8) * QS + ks * 8 + tig];
            af[2] = Pt[r0 * QS + ks * 8 + tig + 4];
            af[3] = Pt[(r0 + 8) * QS + ks * 8 + tig + 4];
#pragma unroll
            for (int nj = 0; nj < 4; nj++) {
                int d0 = wk * 32 + nj * 8 + g;
                unsigned bf[2];
                bf[0] = Vs[(ks * 8 + tig) * VS_ + d0];
                bf[1] = Vs[(ks * 8 + tig + 4) * VS_ + d0];
                mma_tf32(oacc[nj], af, bf);
            }
        }
        __syncthreads();
    }

    // write O (divide by l)
    {
        float li0 = 1.0f / lrow[wq * 16 + g];
        float li1 = 1.0f / lrow[wq * 16 + g + 8];
        int r0 = qb + wq * 16 + g;
#pragma unroll
        for (int nj = 0; nj < 4; nj++) {
            int c = h * HD + wk * 32 + nj * 8 + 2 * tig;
            *(float2*)&y[(size_t)(b * TDIM + r0) * CDIM + c] =
                make_float2(oacc[nj][0] * li0, oacc[nj][1] * li0);
            *(float2*)&y[(size_t)(b * TDIM + r0 + 8) * CDIM + c] =
                make_float2(oacc[nj][2] * li1, oacc[nj][3] * li1);
        }
    }

    // entropy: H_row = m + log(S) - W/S
    if (tid < 64) {
        float S = lrow[tid];
        Ps[tid] = mrow[tid] + logf(S) - wrow[tid] / S;
    }
    __syncthreads();
    if (tid == 0) {
        float tot = 0.f;
        for (int i = 0; i < 64; i++) tot += Ps[i];
        atomicAdd(&g_ent, tot);
    }
}

// ------------------------------------------------------------------
extern "C" void kernel_launch(void* const* d_in, const int* in_sizes, int n_in,
                              void* d_out, int out_size) {
    const float* x          = (const float*)d_in[0];
    const float* ln1_w      = (const float*)d_in[1];
    const float* ln1_b      = (const float*)d_in[2];
    const float* attn_w     = (const float*)d_in[3];
    const float* attn_b     = (const float*)d_in[4];
    const float* attnproj_w = (const float*)d_in[5];
    const float* attnproj_b = (const float*)d_in[6];
    const float* ln2_w      = (const float*)d_in[7];
    const float* ln2_b      = (const float*)d_in[8];
    const float* fc_w       = (const float*)d_in[9];
    const float* fc_b       = (const float*)d_in[10];
    const float* proj_w     = (const float*)d_in[11];
    const float* proj_b     = (const float*)d_in[12];
    float* out = (float*)d_out;

    float *p_h, *p_qkv, *p_y, *p_x1, *p_m;
    cudaGetSymbolAddress((void**)&p_h,   g_h);
    cudaGetSymbolAddress((void**)&p_qkv, g_qkv);
    cudaGetSymbolAddress((void**)&p_y,   g_y);
    cudaGetSymbolAddress((void**)&p_x1,  g_x1);
    cudaGetSymbolAddress((void**)&p_m,   g_m);

    // flash attention dynamic smem: Qt+Ks+Pt+Ps (4*64*68) + Vs (64*72) + 4*64 floats
    static int attn_smem = (4 * 64 * QS + 64 * VS_ + 4 * 64) * 4;
    cudaFuncSetAttribute(flash_attn_tc,
                         cudaFuncAttributeMaxDynamicSharedMemorySize, attn_smem);

    zero_ent_kernel<<<1, 1>>>();

    // h = LN1(x)
    ln_kernel<<<BT, 256>>>(x, ln1_w, ln1_b, p_h);

    // qkv = h @ attn_w^T + attn_b        [4096, 3072]
    gemm_tc<<<dim3(QKVC / 128, BT / 128), 256>>>(
        p_h, attn_w, attn_b, nullptr, p_qkv, BT, QKVC, CDIM, 0);

    // attention (+entropy)
    flash_attn_tc<<<dim3(TDIM / 64, BH), 256, attn_smem>>>(p_qkv, p_y);

    // x1 = x + y @ attnproj_w^T + attnproj_b
    gemm_tc<<<dim3(CDIM / 128, BT / 128), 256>>>(
        p_y, attnproj_w, attnproj_b, x, p_x1, BT, CDIM, CDIM, 0);

    // h = LN2(x1)
    ln_kernel<<<BT, 256>>>(p_x1, ln2_w, ln2_b, p_h);

    // m = gelu(h @ fc_w^T + fc_b)        [4096, 4096]
    gemm_tc<<<dim3(FFC / 128, BT / 128), 256>>>(
        p_h, fc_w, fc_b, nullptr, p_m, BT, FFC, CDIM, 1);

    // out = x1 + m @ proj_w^T + proj_b   -> directly into d_out
    gemm_tc<<<dim3(CDIM / 128, BT / 128), 256>>>(
        p_m, proj_w, proj_b, p_x1, out, BT, CDIM, FFC, 0);

    // entropy scalar
    finalize_kernel<<<1, 1>>>(out, out_size);
}

// round 4
// speedup vs baseline: 8.8524x; 1.1065x over previous
#include <cuda_runtime.h>
#include <math.h>

// Problem constants
#define BATCH 2
#define TDIM 2048
#define CDIM 1024
#define HN 16
#define HD 64
#define BT (BATCH * TDIM)        // 4096 rows
#define BH (BATCH * HN)          // 32 batch-heads
#define QKVC (3 * CDIM)          // 3072
#define FFC (4 * CDIM)           // 4096

#define NEG_BIG (-1e30f)

// -------- scratch (static device globals; no allocation) ----------
__device__ float g_h[BT * CDIM];
__device__ float g_qkv[BT * QKVC];
__device__ float g_y[BT * CDIM];
__device__ float g_x1[BT * CDIM];
__device__ float g_m[BT * FFC];
__device__ float g_ent;

// ------------------------------------------------------------------
__global__ void zero_ent_kernel() { g_ent = 0.0f; }

__global__ void finalize_kernel(float* out, int out_size) {
    if (out_size > BT * CDIM)
        out[BT * CDIM] = g_ent * (1.0f / (float)(BH * TDIM));
}

// -------- cp.async helpers ---------------------------------------
__device__ __forceinline__ void cp16(void* s, const void* g) {
    unsigned sa = (unsigned)__cvta_generic_to_shared(s);
    asm volatile("cp.async.cg.shared.global [%0], [%1], 16;" :: "r"(sa), "l"(g));
}
#define CP_COMMIT() asm volatile("cp.async.commit_group;")
#define CP_WAIT0()  asm volatile("cp.async.wait_group 0;")

// -------- LayerNorm ----------------------------------------------
__global__ void ln_kernel(const float* __restrict__ x,
                          const float* __restrict__ w,
                          const float* __restrict__ b,
                          float* __restrict__ out) {
    int row = blockIdx.x;
    int tid = threadIdx.x;
    const float* xr = x + (size_t)row * CDIM;
    __shared__ float red[256];

    float v[4];
    float lsum = 0.f, lsq = 0.f;
#pragma unroll
    for (int i = 0; i < 4; i++) {
        v[i] = xr[tid + i * 256];
        lsum += v[i];
        lsq  += v[i] * v[i];
    }
    red[tid] = lsum; __syncthreads();
    for (int s = 128; s > 0; s >>= 1) {
        if (tid < s) red[tid] += red[tid + s];
        __syncthreads();
    }
    float mean = red[0] * (1.0f / CDIM);
    __syncthreads();
    red[tid] = lsq; __syncthreads();
    for (int s = 128; s > 0; s >>= 1) {
        if (tid < s) red[tid] += red[tid + s];
        __syncthreads();
    }
    float var = red[0] * (1.0f / CDIM) - mean * mean;
    float rstd = rsqrtf(var + 1e-5f);
#pragma unroll
    for (int i = 0; i < 4; i++) {
        int c = tid + i * 256;
        out[(size_t)row * CDIM + c] = (v[i] - mean) * rstd * w[c] + b[c];
    }
}

// -------- MMA (raw f32 bits as tf32: HW ignores low 13 mantissa bits)
__device__ __forceinline__ void mma_tf32(float* c, const unsigned* a, const unsigned* b) {
    asm("mma.sync.aligned.m16n8k8.row.col.f32.tf32.tf32.f32 "
        "{%0,%1,%2,%3}, {%4,%5,%6,%7}, {%8,%9}, {%0,%1,%2,%3};"
        : "+f"(c[0]), "+f"(c[1]), "+f"(c[2]), "+f"(c[3])
        : "r"(a[0]), "r"(a[1]), "r"(a[2]), "r"(a[3]), "r"(b[0]), "r"(b[1]));
}

__device__ __forceinline__ float gelu_tanh(float x) {
    const float k0 = 0.7978845608028654f;
    const float k1 = 0.044715f;
    float u = k0 * (x + k1 * x * x * x);
    // tanh(u) = (e^{2u}-1)/(e^{2u}+1) via fast exp
    float t = __expf(2.0f * u);
    float th = (t - 1.0f) / (t + 1.0f);
    return 0.5f * x * (1.0f + th);
}

// -------- tf32 tensor-core GEMM: C = A[M,K]*W[N,K]^T + bias --------
// 128x128x32 tile, 256 threads, warp grid 2(m)x4(n), warp tile 64x32.
// cp.async double-buffered; raw f32 in smem (used as tf32).
#define GST 36                       // smem row stride (floats); 144B, 16B-aligned
#define GBUF (128 * GST)

__global__ __launch_bounds__(256)
void gemm_tc(const float* __restrict__ A, const float* __restrict__ W,
             const float* __restrict__ bias, const float* __restrict__ resid,
             float* __restrict__ C, int M, int N, int K, int act) {
    extern __shared__ float sm[];
    float* As = sm;                  // [2][128][36]
    float* Ws = sm + 2 * GBUF;       // [2][128][36]

    int tid = threadIdx.x;
    int warp = tid >> 5, lane = tid & 31;
    int wm = warp >> 2, wn = warp & 3;
    int g = lane >> 2, tig = lane & 3;
    int rowBase = blockIdx.y * 128, colBase = blockIdx.x * 128;
    const float* Ap = A + (size_t)rowBase * K;
    const float* Wp = W + (size_t)colBase * K;

    float acc[4][4][4];
#pragma unroll
    for (int i = 0; i < 4; i++)
#pragma unroll
        for (int j = 0; j < 4; j++)
#pragma unroll
            for (int p = 0; p < 4; p++) acc[i][j][p] = 0.f;

    int lr = tid >> 3;               // 0..31? no: tid/8 -> 0..31 (x4 iters covers 128)
    int lc = (tid & 7) * 4;          // 0,4,...28

    // prefetch tile 0
#pragma unroll
    for (int it = 0; it < 4; it++) {
        int r = lr + it * 32;
        cp16(&As[r * GST + lc], Ap + (size_t)r * K + lc);
        cp16(&Ws[r * GST + lc], Wp + (size_t)r * K + lc);
    }
    CP_COMMIT();

    int nt = K >> 5;
    for (int t = 0; t < nt; t++) {
        CP_WAIT0();
        __syncthreads();
        if (t + 1 < nt) {
            int kt = (t + 1) << 5;
            int nb = (t + 1) & 1;
#pragma unroll
            for (int it = 0; it < 4; it++) {
                int r = lr + it * 32;
                cp16(&As[nb * GBUF + r * GST + lc], Ap + (size_t)r * K + kt + lc);
                cp16(&Ws[nb * GBUF + r * GST + lc], Wp + (size_t)r * K + kt + lc);
            }
            CP_COMMIT();
        }
        const float* Ab = As + (t & 1) * GBUF;
        const float* Wb = Ws + (t & 1) * GBUF;
#pragma unroll
        for (int ks = 0; ks < 4; ks++) {
            unsigned af[4][4], bf[4][2];
#pragma unroll
            for (int mi = 0; mi < 4; mi++) {
                int r0 = wm * 64 + mi * 16 + g;
                af[mi][0] = __float_as_uint(Ab[r0 * GST + ks * 8 + tig]);
                af[mi][1] = __float_as_uint(Ab[(r0 + 8) * GST + ks * 8 + tig]);
                af[mi][2] = __float_as_uint(Ab[r0 * GST + ks * 8 + tig + 4]);
                af[mi][3] = __float_as_uint(Ab[(r0 + 8) * GST + ks * 8 + tig + 4]);
            }
#pragma unroll
            for (int nj = 0; nj < 4; nj++) {
                int c0 = wn * 32 + nj * 8 + g;
                bf[nj][0] = __float_as_uint(Wb[c0 * GST + ks * 8 + tig]);
                bf[nj][1] = __float_as_uint(Wb[c0 * GST + ks * 8 + tig + 4]);
            }
#pragma unroll
            for (int mi = 0; mi < 4; mi++)
#pragma unroll
                for (int nj = 0; nj < 4; nj++)
                    mma_tf32(acc[mi][nj], af[mi], bf[nj]);
        }
        __syncthreads();
    }

    // epilogue
#pragma unroll
    for (int mi = 0; mi < 4; mi++) {
#pragma unroll
        for (int h2 = 0; h2 < 2; h2++) {
            int r = rowBase + wm * 64 + mi * 16 + g + h2 * 8;
            float* crow = C + (size_t)r * N;
            const float* rrow = resid ? resid + (size_t)r * N : nullptr;
#pragma unroll
            for (int nj = 0; nj < 4; nj++) {
                int c = colBase + wn * 32 + nj * 8 + 2 * tig;
                float v0 = acc[mi][nj][h2 * 2]     + bias[c];
                float v1 = acc[mi][nj][h2 * 2 + 1] + bias[c + 1];
                if (act == 1) { v0 = gelu_tanh(v0); v1 = gelu_tanh(v1); }
                if (rrow) { v0 += rrow[c]; v1 += rrow[c + 1]; }
                *(float2*)&crow[c] = make_float2(v0, v1);
            }
        }
    }
}

// -------- Flash attention, tf32 MMA, cp.async double-buffered K/V --
#define QS 68      // stride Qs/Ps (272B, 16B-aligned, conflict-free frags)
#define VS_ 72     // stride Vs (288B, 16B-aligned)
#define KBUF (64 * QS)
#define VBUF (64 * VS_)

__global__ __launch_bounds__(256)
void flash_attn_tc(const float* __restrict__ qkv, float* __restrict__ y) {
    extern __shared__ float smf[];
    float* Qs = smf;                   // [64][68]
    float* Ks = Qs + KBUF;             // [2][64][68]
    float* Vs = Ks + 2 * KBUF;         // [2][64][72]
    float* Ps = Vs + 2 * VBUF;         // [64][68] scores -> probs (in place)
    float* mrow = Ps + KBUF;
    float* lrow = mrow + 64;
    float* wrow = lrow + 64;
    float* cf   = wrow + 64;

    int tid = threadIdx.x;
    int warp = tid >> 5, lane = tid & 31;
    int g = lane >> 2, tig = lane & 3;
    int qt = blockIdx.x, bh = blockIdx.y;
    int b = bh >> 4, h = bh & 15;
    int qb = qt * 64;
    const float* base = qkv + (size_t)b * TDIM * QKVC + h * HD;

    int wq = warp >> 1;   // 0..3 : 16 q rows
    int wk = warp & 1;    // 0..1 : 32 cols

    int lr = tid >> 2;          // 0..63
    int lc = (tid & 3) * 4;     // 0,4,8,12  (x4 iters covers 64)

    // prefetch Q + K0 + V0 (one group)
#pragma unroll
    for (int it = 0; it < 4; it++) {
        int c = lc + it * 16;
        cp16(&Qs[lr * QS + c], &base[(size_t)(qb + lr) * QKVC + c]);
        cp16(&Ks[lr * QS + c], &base[(size_t)lr * QKVC + CDIM + c]);
        cp16(&Vs[lr * VS_ + c], &base[(size_t)lr * QKVC + 2 * CDIM + c]);
    }
    CP_COMMIT();

    if (tid < 64) { mrow[tid] = NEG_BIG; lrow[tid] = 0.f; wrow[tid] = 0.f; }

    float oacc[4][4];
#pragma unroll
    for (int nj = 0; nj < 4; nj++)
#pragma unroll
        for (int p = 0; p < 4; p++) oacc[nj][p] = 0.f;

    CP_WAIT0();
    __syncthreads();

    // hoist Q fragments (loop-invariant)
    unsigned qf[8][4];
#pragma unroll
    for (int ks = 0; ks < 8; ks++) {
        int r0 = wq * 16 + g;
        qf[ks][0] = __float_as_uint(Qs[r0 * QS + ks * 8 + tig]);
        qf[ks][1] = __float_as_uint(Qs[(r0 + 8) * QS + ks * 8 + tig]);
        qf[ks][2] = __float_as_uint(Qs[r0 * QS + ks * 8 + tig + 4]);
        qf[ks][3] = __float_as_uint(Qs[(r0 + 8) * QS + ks * 8 + tig + 4]);
    }

    int ni = qt + 1;
    for (int i = 0; i < ni; i++) {
        CP_WAIT0();
        __syncthreads();
        if (i + 1 < ni) {
            int nb = (i + 1) & 1;
            int kb = (i + 1) * 64;
#pragma unroll
            for (int it = 0; it < 4; it++) {
                int c = lc + it * 16;
                cp16(&Ks[nb * KBUF + lr * QS + c],
                     &base[(size_t)(kb + lr) * QKVC + CDIM + c]);
                cp16(&Vs[nb * VBUF + lr * VS_ + c],
                     &base[(size_t)(kb + lr) * QKVC + 2 * CDIM + c]);
            }
            CP_COMMIT();
        }
        const float* Kb = Ks + (i & 1) * KBUF;
        const float* Vb = Vs + (i & 1) * VBUF;

        // ---- S = Q K^T : warp tile 16q x 32k ----
        float sacc[4][4];
#pragma unroll
        for (int nj = 0; nj < 4; nj++)
#pragma unroll
            for (int p = 0; p < 4; p++) sacc[nj][p] = 0.f;
#pragma unroll
        for (int ks = 0; ks < 8; ks++) {
#pragma unroll
            for (int nj = 0; nj < 4; nj++) {
                int c0 = wk * 32 + nj * 8 + g;
                unsigned bf[2];
                bf[0] = __float_as_uint(Kb[c0 * QS + ks * 8 + tig]);
                bf[1] = __float_as_uint(Kb[c0 * QS + ks * 8 + tig + 4]);
                mma_tf32(sacc[nj], qf[ks], bf);
            }
        }
        bool diag = (i == qt);
#pragma unroll
        for (int nj = 0; nj < 4; nj++) {
            int c0 = wk * 32 + nj * 8 + 2 * tig;
#pragma unroll
            for (int h2 = 0; h2 < 2; h2++) {
                int r = wq * 16 + g + h2 * 8;
                float s0 = sacc[nj][h2 * 2] * 0.125f;
                float s1 = sacc[nj][h2 * 2 + 1] * 0.125f;
                if (diag) {
                    if (c0 > r) s0 = NEG_BIG;
                    if (c0 + 1 > r) s1 = NEG_BIG;
                }
                Ps[r * QS + c0] = s0;
                Ps[r * QS + c0 + 1] = s1;
            }
        }
        __syncthreads();

        // ---- online softmax (in place: scores -> probs) ----
#pragma unroll
        for (int r = 0; r < 8; r++) {
            int qq = warp * 8 + r;
            float s0 = Ps[qq * QS + lane];
            float s1 = Ps[qq * QS + 32 + lane];
            float tmx = fmaxf(s0, s1);
#pragma unroll
            for (int o = 16; o > 0; o >>= 1)
                tmx = fmaxf(tmx, __shfl_xor_sync(0xFFFFFFFFu, tmx, o));
            float mold = mrow[qq];
            float mnew = fmaxf(mold, tmx);
            float e0 = __expf(s0 - mnew);
            float e1 = __expf(s1 - mnew);
            float se = e0 + e1;
            float sw = e0 * s0 + e1 * s1;
#pragma unroll
            for (int o = 16; o > 0; o >>= 1) {
                se += __shfl_xor_sync(0xFFFFFFFFu, se, o);
                sw += __shfl_xor_sync(0xFFFFFFFFu, sw, o);
            }
            float c = __expf(mold - mnew);
            if (lane == 0) {
                mrow[qq] = mnew;
                lrow[qq] = lrow[qq] * c + se;
                wrow[qq] = wrow[qq] * c + sw;
                cf[qq] = c;
            }
            Ps[qq * QS + lane] = e0;
            Ps[qq * QS + 32 + lane] = e1;
        }
        __syncthreads();

        // ---- O = O*c + P V : warp tile 16q x 32d ----
        float c0f = cf[wq * 16 + g];
        float c1f = cf[wq * 16 + g + 8];
#pragma unroll
        for (int nj = 0; nj < 4; nj++) {
            oacc[nj][0] *= c0f; oacc[nj][1] *= c0f;
            oacc[nj][2] *= c1f; oacc[nj][3] *= c1f;
        }
#pragma unroll
        for (int ks = 0; ks < 8; ks++) {
            unsigned af[4];
            int r0 = wq * 16 + g;
            af[0] = __float_as_uint(Ps[r0 * QS + ks * 8 + tig]);
            af[1] = __float_as_uint(Ps[(r0 + 8) * QS + ks * 8 + tig]);
            af[2] = __float_as_uint(Ps[r0 * QS + ks * 8 + tig + 4]);
            af[3] = __float_as_uint(Ps[(r0 + 8) * QS + ks * 8 + tig + 4]);
#pragma unroll
            for (int nj = 0; nj < 4; nj++) {
                int d0 = wk * 32 + nj * 8 + g;
                unsigned bf[2];
                bf[0] = __float_as_uint(Vb[(ks * 8 + tig) * VS_ + d0]);
                bf[1] = __float_as_uint(Vb[(ks * 8 + tig + 4) * VS_ + d0]);
                mma_tf32(oacc[nj], af, bf);
            }
        }
        __syncthreads();
    }

    // write O (divide by l)
    {
        float li0 = 1.0f / lrow[wq * 16 + g];
        float li1 = 1.0f / lrow[wq * 16 + g + 8];
        int r0 = qb + wq * 16 + g;
#pragma unroll
        for (int nj = 0; nj < 4; nj++) {
            int c = h * HD + wk * 32 + nj * 8 + 2 * tig;
            *(float2*)&y[(size_t)(b * TDIM + r0) * CDIM + c] =
                make_float2(oacc[nj][0] * li0, oacc[nj][1] * li0);
            *(float2*)&y[(size_t)(b * TDIM + r0 + 8) * CDIM + c] =
                make_float2(oacc[nj][2] * li1, oacc[nj][3] * li1);
        }
    }

    // entropy: H_row = m + log(S) - W/S
    if (tid < 64) {
        float S = lrow[tid];
        Ps[tid] = mrow[tid] + logf(S) - wrow[tid] / S;
    }
    __syncthreads();
    if (tid == 0) {
        float tot = 0.f;
        for (int i = 0; i < 64; i++) tot += Ps[i];
        atomicAdd(&g_ent, tot);
    }
}

// ------------------------------------------------------------------
extern "C" void kernel_launch(void* const* d_in, const int* in_sizes, int n_in,
                              void* d_out, int out_size) {
    const float* x          = (const float*)d_in[0];
    const float* ln1_w      = (const float*)d_in[1];
    const float* ln1_b      = (const float*)d_in[2];
    const float* attn_w     = (const float*)d_in[3];
    const float* attn_b     = (const float*)d_in[4];
    const float* attnproj_w = (const float*)d_in[5];
    const float* attnproj_b = (const float*)d_in[6];
    const float* ln2_w      = (const float*)d_in[7];
    const float* ln2_b      = (const float*)d_in[8];
    const float* fc_w       = (const float*)d_in[9];
    const float* fc_b       = (const float*)d_in[10];
    const float* proj_w     = (const float*)d_in[11];
    const float* proj_b     = (const float*)d_in[12];
    float* out = (float*)d_out;

    float *p_h, *p_qkv, *p_y, *p_x1, *p_m;
    cudaGetSymbolAddress((void**)&p_h,   g_h);
    cudaGetSymbolAddress((void**)&p_qkv, g_qkv);
    cudaGetSymbolAddress((void**)&p_y,   g_y);
    cudaGetSymbolAddress((void**)&p_x1,  g_x1);
    cudaGetSymbolAddress((void**)&p_m,   g_m);

    static int gemm_smem = 4 * GBUF * 4;                       // 73728 B
    static int attn_smem = (3 * KBUF + KBUF + 2 * VBUF + 256) * 4;  // Qs+Ps+2K+2V
    cudaFuncSetAttribute(gemm_tc,
                         cudaFuncAttributeMaxDynamicSharedMemorySize, gemm_smem);
    cudaFuncSetAttribute(flash_attn_tc,
                         cudaFuncAttributeMaxDynamicSharedMemorySize, attn_smem);

    zero_ent_kernel<<<1, 1>>>();

    // h = LN1(x)
    ln_kernel<<<BT, 256>>>(x, ln1_w, ln1_b, p_h);

    // qkv = h @ attn_w^T + attn_b
    gemm_tc<<<dim3(QKVC / 128, BT / 128), 256, gemm_smem>>>(
        p_h, attn_w, attn_b, nullptr, p_qkv, BT, QKVC, CDIM, 0);

    // attention (+entropy)
    flash_attn_tc<<<dim3(TDIM / 64, BH), 256, attn_smem>>>(p_qkv, p_y);

    // x1 = x + y @ attnproj_w^T + attnproj_b
    gemm_tc<<<dim3(CDIM / 128, BT / 128), 256, gemm_smem>>>(
        p_y, attnproj_w, attnproj_b, x, p_x1, BT, CDIM, CDIM, 0);

    // h = LN2(x1)
    ln_kernel<<<BT, 256>>>(p_x1, ln2_w, ln2_b, p_h);

    // m = gelu(h @ fc_w^T + fc_b)
    gemm_tc<<<dim3(FFC / 128, BT / 128), 256, gemm_smem>>>(
        p_h, fc_w, fc_b, nullptr, p_m, BT, FFC, CDIM, 1);

    // out = x1 + m @ proj_w^T + proj_b
    gemm_tc<<<dim3(CDIM / 128, BT / 128), 256, gemm_smem>>>(
        p_m, proj_w, proj_b, p_x1, out, BT, CDIM, FFC, 0);

    // entropy scalar
    finalize_kernel<<<1, 1>>>(out, out_size);
}

// round 6
// speedup vs baseline: 9.7543x; 1.1019x over previous
#include <cuda_runtime.h>
#include <math.h>
#include <stdint.h>

// Problem constants
#define BATCH 2
#define TDIM 2048
#define CDIM 1024
#define HN 16
#define HD 64
#define BT (BATCH * TDIM)        // 4096 rows
#define BH (BATCH * HN)          // 32 batch-heads
#define QKVC (3 * CDIM)          // 3072
#define FFC (4 * CDIM)           // 4096

#define NEG_BIG (-1e30f)

// -------- scratch (static device globals; no allocation) ----------
__device__ float g_h[BT * CDIM];
__device__ float g_qkv[BT * QKVC];
__device__ float g_y[BT * CDIM];
__device__ float g_x1[BT * CDIM];
__device__ float g_m[BT * FFC];
__device__ float g_wr[12582912];   // RN-rounded weights: attn|attnproj|fc|proj
__device__ float g_ent;

#define WR_ATTN  0
#define WR_APROJ 3145728
#define WR_FC    4194304
#define WR_PROJ  8388608

// ------------------------------------------------------------------
__global__ void zero_ent_kernel() { g_ent = 0.0f; }

__global__ void finalize_kernel(float* out, int out_size) {
    if (out_size > BT * CDIM)
        out[BT * CDIM] = g_ent * (1.0f / (float)(BH * TDIM));
}

// -------- helpers -------------------------------------------------
__device__ __forceinline__ float rtf(float x) {   // round-to-nearest tf32
    uint32_t u; asm("cvt.rna.tf32.f32 %0, %1;" : "=r"(u) : "f"(x));
    return __uint_as_float(u);
}

__device__ __forceinline__ void cp16(void* s, const void* g) {
    unsigned sa = (unsigned)__cvta_generic_to_shared(s);
    asm volatile("cp.async.cg.shared.global [%0], [%1], 16;" :: "r"(sa), "l"(g));
}
#define CP_COMMIT() asm volatile("cp.async.commit_group;")
#define CP_WAIT0()  asm volatile("cp.async.wait_group 0;")

__device__ __forceinline__ void mma_tf32(float* c, const unsigned* a, const unsigned* b) {
    asm("mma.sync.aligned.m16n8k8.row.col.f32.tf32.tf32.f32 "
        "{%0,%1,%2,%3}, {%4,%5,%6,%7}, {%8,%9}, {%0,%1,%2,%3};"
        : "+f"(c[0]), "+f"(c[1]), "+f"(c[2]), "+f"(c[3])
        : "r"(a[0]), "r"(a[1]), "r"(a[2]), "r"(a[3]), "r"(b[0]), "r"(b[1]));
}

// -------- weight rounding kernel ---------------------------------
__global__ void round4_kernel(const float* __restrict__ in,
                              float* __restrict__ out, int n) {
    int i = (blockIdx.x * blockDim.x + threadIdx.x) * 4;
    if (i < n) {
        float4 v = *(const float4*)&in[i];
        v.x = rtf(v.x); v.y = rtf(v.y); v.z = rtf(v.z); v.w = rtf(v.w);
        *(float4*)&out[i] = v;
    }
}

// -------- LayerNorm (RN-rounds output to tf32) --------------------
__global__ void ln_kernel(const float* __restrict__ x,
                          const float* __restrict__ w,
                          const float* __restrict__ b,
                          float* __restrict__ out) {
    int row = blockIdx.x;
    int tid = threadIdx.x;
    const float* xr = x + (size_t)row * CDIM;
    __shared__ float red[256];

    float v[4];
    float lsum = 0.f, lsq = 0.f;
#pragma unroll
    for (int i = 0; i < 4; i++) {
        v[i] = xr[tid + i * 256];
        lsum += v[i];
        lsq  += v[i] * v[i];
    }
    red[tid] = lsum; __syncthreads();
    for (int s = 128; s > 0; s >>= 1) {
        if (tid < s) red[tid] += red[tid + s];
        __syncthreads();
    }
    float mean = red[0] * (1.0f / CDIM);
    __syncthreads();
    red[tid] = lsq; __syncthreads();
    for (int s = 128; s > 0; s >>= 1) {
        if (tid < s) red[tid] += red[tid + s];
        __syncthreads();
    }
    float var = red[0] * (1.0f / CDIM) - mean * mean;
    float rstd = rsqrtf(var + 1e-5f);
#pragma unroll
    for (int i = 0; i < 4; i++) {
        int c = tid + i * 256;
        out[(size_t)row * CDIM + c] = rtf((v[i] - mean) * rstd * w[c] + b[c]);
    }
}

__device__ __forceinline__ float gelu_tanh(float x) {
    const float k0 = 0.7978845608028654f;
    const float k1 = 0.044715f;
    float u = k0 * (x + k1 * x * x * x);
    float t = __expf(2.0f * u);
    float th = (t - 1.0f) / (t + 1.0f);
    return 0.5f * x * (1.0f + th);
}

// -------- tf32 tensor-core GEMM: C = A[M,K]*W[N,K]^T + bias --------
// 128x128x32 tile, 256 threads, warp grid 2(m)x4(n), warp tile 64x32.
// cp.async double-buffered; raw pre-rounded f32 in smem (used as tf32).
#define GST 36
#define GBUF (128 * GST)

__global__ __launch_bounds__(256)
void gemm_tc(const float* __restrict__ A, const float* __restrict__ W,
             const float* __restrict__ bias, const float* __restrict__ resid,
             float* __restrict__ C, int M, int N, int K, int act, int rnd) {
    extern __shared__ float sm[];
    float* As = sm;
    float* Ws = sm + 2 * GBUF;

    int tid = threadIdx.x;
    int warp = tid >> 5, lane = tid & 31;
    int wm = warp >> 2, wn = warp & 3;
    int g = lane >> 2, tig = lane & 3;
    int rowBase = blockIdx.y * 128, colBase = blockIdx.x * 128;
    const float* Ap = A + (size_t)rowBase * K;
    const float* Wp = W + (size_t)colBase * K;

    float acc[4][4][4];
#pragma unroll
    for (int i = 0; i < 4; i++)
#pragma unroll
        for (int j = 0; j < 4; j++)
#pragma unroll
            for (int p = 0; p < 4; p++) acc[i][j][p] = 0.f;

    int lr = tid >> 3;
    int lc = (tid & 7) * 4;

#pragma unroll
    for (int it = 0; it < 4; it++) {
        int r = lr + it * 32;
        cp16(&As[r * GST + lc], Ap + (size_t)r * K + lc);
        cp16(&Ws[r * GST + lc], Wp + (size_t)r * K + lc);
    }
    CP_COMMIT();

    int nt = K >> 5;
    for (int t = 0; t < nt; t++) {
        CP_WAIT0();
        __syncthreads();
        if (t + 1 < nt) {
            int kt = (t + 1) << 5;
            int nb = (t + 1) & 1;
#pragma unroll
            for (int it = 0; it < 4; it++) {
                int r = lr + it * 32;
                cp16(&As[nb * GBUF + r * GST + lc], Ap + (size_t)r * K + kt + lc);
                cp16(&Ws[nb * GBUF + r * GST + lc], Wp + (size_t)r * K + kt + lc);
            }
            CP_COMMIT();
        }
        const float* Ab = As + (t & 1) * GBUF;
        const float* Wb = Ws + (t & 1) * GBUF;
#pragma unroll
        for (int ks = 0; ks < 4; ks++) {
            unsigned af[4][4], bf[4][2];
#pragma unroll
            for (int mi = 0; mi < 4; mi++) {
                int r0 = wm * 64 + mi * 16 + g;
                af[mi][0] = __float_as_uint(Ab[r0 * GST + ks * 8 + tig]);
                af[mi][1] = __float_as_uint(Ab[(r0 + 8) * GST + ks * 8 + tig]);
                af[mi][2] = __float_as_uint(Ab[r0 * GST + ks * 8 + tig + 4]);
                af[mi][3] = __float_as_uint(Ab[(r0 + 8) * GST + ks * 8 + tig + 4]);
            }
#pragma unroll
            for (int nj = 0; nj < 4; nj++) {
                int c0 = wn * 32 + nj * 8 + g;
                bf[nj][0] = __float_as_uint(Wb[c0 * GST + ks * 8 + tig]);
                bf[nj][1] = __float_as_uint(Wb[c0 * GST + ks * 8 + tig + 4]);
            }
#pragma unroll
            for (int mi = 0; mi < 4; mi++)
#pragma unroll
                for (int nj = 0; nj < 4; nj++)
                    mma_tf32(acc[mi][nj], af[mi], bf[nj]);
        }
        __syncthreads();
    }

    // epilogue
#pragma unroll
    for (int mi = 0; mi < 4; mi++) {
#pragma unroll
        for (int h2 = 0; h2 < 2; h2++) {
            int r = rowBase + wm * 64 + mi * 16 + g + h2 * 8;
            float* crow = C + (size_t)r * N;
            const float* rrow = resid ? resid + (size_t)r * N : nullptr;
#pragma unroll
            for (int nj = 0; nj < 4; nj++) {
                int c = colBase + wn * 32 + nj * 8 + 2 * tig;
                float v0 = acc[mi][nj][h2 * 2]     + bias[c];
                float v1 = acc[mi][nj][h2 * 2 + 1] + bias[c + 1];
                if (act == 1) { v0 = gelu_tanh(v0); v1 = gelu_tanh(v1); }
                if (rrow) { v0 += rrow[c]; v1 += rrow[c + 1]; }
                if (rnd) { v0 = rtf(v0); v1 = rtf(v1); }
                *(float2*)&crow[c] = make_float2(v0, v1);
            }
        }
    }
}

// -------- Flash attention: 128q x 64k tiles, per-warp pipeline -----
// 8 warps, warp owns 16 q rows end-to-end. Scores stay in registers;
// softmax via quad shuffles; P transits smem once (PV A-frag layout).
#define QS 68
#define VSS 72
#define KB1 (64 * QS)
#define VB1 (64 * VSS)

__global__ __launch_bounds__(256)
void flash_attn_tc(const float* __restrict__ qkv, float* __restrict__ y) {
    extern __shared__ float smf[];
    float* Ks = smf;                  // [2][64][68]
    float* Vs = Ks + 2 * KB1;         // [2][64][72]
    float* Ps = Vs + 2 * VB1;         // [128][68]  Q staging, then P probs
    float* hrow = Ps + 128 * QS;      // [128]

    int tid = threadIdx.x;
    int warp = tid >> 5, lane = tid & 31;
    int g = lane >> 2, tig = lane & 3;
    int qt = (TDIM / 128 - 1) - blockIdx.x;   // long tiles first
    int bh = blockIdx.y;
    int b = bh >> 4, h = bh & 15;
    int qb = qt * 128;
    const float* base = qkv + (size_t)b * TDIM * QKVC + h * HD;

    // prefetch Q (128x64 -> Ps) + K0 + V0
#pragma unroll
    for (int i = 0; i < 8; i++) {
        int ch = tid + i * 256; int r = ch >> 4; int c = (ch & 15) * 4;
        cp16(&Ps[r * QS + c], &base[(size_t)(qb + r) * QKVC + c]);
    }
#pragma unroll
    for (int i = 0; i < 4; i++) {
        int ch = tid + i * 256; int r = ch >> 4; int c = (ch & 15) * 4;
        cp16(&Ks[r * QS + c], &base[(size_t)r * QKVC + CDIM + c]);
        cp16(&Vs[r * VSS + c], &base[(size_t)r * QKVC + 2 * CDIM + c]);
    }
    CP_COMMIT();
    CP_WAIT0();
    __syncthreads();

    // hoist Q fragments (warp's 16 rows x 64 d)
    int r0l = warp * 16 + g;
    unsigned qf[8][4];
#pragma unroll
    for (int ks = 0; ks < 8; ks++) {
        qf[ks][0] = __float_as_uint(Ps[r0l * QS + ks * 8 + tig]);
        qf[ks][1] = __float_as_uint(Ps[(r0l + 8) * QS + ks * 8 + tig]);
        qf[ks][2] = __float_as_uint(Ps[r0l * QS + ks * 8 + tig + 4]);
        qf[ks][3] = __float_as_uint(Ps[(r0l + 8) * QS + ks * 8 + tig + 4]);
    }

    float m0 = NEG_BIG, m1 = NEG_BIG, l0 = 0.f, l1 = 0.f, w0 = 0.f, w1 = 0.f;
    float oacc[8][4];
#pragma unroll
    for (int nj = 0; nj < 8; nj++)
#pragma unroll
        for (int p = 0; p < 4; p++) oacc[nj][p] = 0.f;

    int row0 = qb + warp * 16 + g, row1 = row0 + 8;
    int ni = 2 * qt + 2;

    for (int i = 0; i < ni; i++) {
        CP_WAIT0();
        __syncthreads();
        if (i + 1 < ni) {
            int nb = (i + 1) & 1, kb2 = (i + 1) * 64;
#pragma unroll
            for (int it = 0; it < 4; it++) {
                int ch = tid + it * 256; int r = ch >> 4; int c = (ch & 15) * 4;
                cp16(&Ks[nb * KB1 + r * QS + c],
                     &base[(size_t)(kb2 + r) * QKVC + CDIM + c]);
                cp16(&Vs[nb * VB1 + r * VSS + c],
                     &base[(size_t)(kb2 + r) * QKVC + 2 * CDIM + c]);
            }
            CP_COMMIT();
        }
        int kb = i * 64;
        if (qb + warp * 16 + 15 >= kb) {   // warp has unmasked rows in this tile
            const float* Kb = Ks + (i & 1) * KB1;
            const float* Vb = Vs + (i & 1) * VB1;

            // ---- S = Q K^T (registers) ----
            float sacc[8][4];
#pragma unroll
            for (int nj = 0; nj < 8; nj++)
#pragma unroll
                for (int p = 0; p < 4; p++) sacc[nj][p] = 0.f;
#pragma unroll
            for (int ks = 0; ks < 8; ks++) {
#pragma unroll
                for (int nj = 0; nj < 8; nj++) {
                    int c0 = nj * 8 + g;
                    unsigned bf[2];
                    bf[0] = __float_as_uint(Kb[c0 * QS + ks * 8 + tig]);
                    bf[1] = __float_as_uint(Kb[c0 * QS + ks * 8 + tig + 4]);
                    mma_tf32(sacc[nj], qf[ks], bf);
                }
            }

            // ---- scale + mask + row max ----
            float mx0 = NEG_BIG, mx1 = NEG_BIG;
#pragma unroll
            for (int nj = 0; nj < 8; nj++) {
                int cg = kb + nj * 8 + 2 * tig;
                float s0 = sacc[nj][0] * 0.125f;
                float s1 = sacc[nj][1] * 0.125f;
                float s2 = sacc[nj][2] * 0.125f;
                float s3 = sacc[nj][3] * 0.125f;
                if (cg > row0) s0 = NEG_BIG;
                if (cg + 1 > row0) s1 = NEG_BIG;
                if (cg > row1) s2 = NEG_BIG;
                if (cg + 1 > row1) s3 = NEG_BIG;
                sacc[nj][0] = s0; sacc[nj][1] = s1;
                sacc[nj][2] = s2; sacc[nj][3] = s3;
                mx0 = fmaxf(mx0, fmaxf(s0, s1));
                mx1 = fmaxf(mx1, fmaxf(s2, s3));
            }
            mx0 = fmaxf(mx0, __shfl_xor_sync(0xFFFFFFFFu, mx0, 1));
            mx0 = fmaxf(mx0, __shfl_xor_sync(0xFFFFFFFFu, mx0, 2));
            mx1 = fmaxf(mx1, __shfl_xor_sync(0xFFFFFFFFu, mx1, 1));
            mx1 = fmaxf(mx1, __shfl_xor_sync(0xFFFFFFFFu, mx1, 2));
            float mn0 = fmaxf(m0, mx0), mn1 = fmaxf(m1, mx1);

            // ---- exp + sums + write P ----
            float se0 = 0.f, se1 = 0.f, sw0 = 0.f, sw1 = 0.f;
#pragma unroll
            for (int nj = 0; nj < 8; nj++) {
                float s0 = sacc[nj][0], s1 = sacc[nj][1];
                float s2 = sacc[nj][2], s3 = sacc[nj][3];
                float e0 = __expf(s0 - mn0), e1 = __expf(s1 - mn0);
                float e2 = __expf(s2 - mn1), e3 = __expf(s3 - mn1);
                se0 += e0 + e1; sw0 += e0 * s0 + e1 * s1;
                se1 += e2 + e3; sw1 += e2 * s2 + e3 * s3;
                int c0 = nj * 8 + 2 * tig;
                *(float2*)&Ps[(warp * 16 + g) * QS + c0] =
                    make_float2(rtf(e0), rtf(e1));
                *(float2*)&Ps[(warp * 16 + g + 8) * QS + c0] =
                    make_float2(rtf(e2), rtf(e3));
            }
            se0 += __shfl_xor_sync(0xFFFFFFFFu, se0, 1);
            se0 += __shfl_xor_sync(0xFFFFFFFFu, se0, 2);
            sw0 += __shfl_xor_sync(0xFFFFFFFFu, sw0, 1);
            sw0 += __shfl_xor_sync(0xFFFFFFFFu, sw0, 2);
            se1 += __shfl_xor_sync(0xFFFFFFFFu, se1, 1);
            se1 += __shfl_xor_sync(0xFFFFFFFFu, se1, 2);
            sw1 += __shfl_xor_sync(0xFFFFFFFFu, sw1, 1);
            sw1 += __shfl_xor_sync(0xFFFFFFFFu, sw1, 2);

            float c0f = __expf(m0 - mn0), c1f = __expf(m1 - mn1);
            l0 = l0 * c0f + se0; w0 = w0 * c0f + sw0; m0 = mn0;
            l1 = l1 * c1f + se1; w1 = w1 * c1f + sw1; m1 = mn1;
#pragma unroll
            for (int nj = 0; nj < 8; nj++) {
                oacc[nj][0] *= c0f; oacc[nj][1] *= c0f;
                oacc[nj][2] *= c1f; oacc[nj][3] *= c1f;
            }
            __syncwarp();

            // ---- O += P V ----
#pragma unroll
            for (int ks = 0; ks < 8; ks++) {
                unsigned af[4];
                af[0] = __float_as_uint(Ps[r0l * QS + ks * 8 + tig]);
                af[1] = __float_as_uint(Ps[(r0l + 8) * QS + ks * 8 + tig]);
                af[2] = __float_as_uint(Ps[r0l * QS + ks * 8 + tig + 4]);
                af[3] = __float_as_uint(Ps[(r0l + 8) * QS + ks * 8 + tig + 4]);
#pragma unroll
                for (int nj = 0; nj < 8; nj++) {
                    int d0 = nj * 8 + g;
                    unsigned bf[2];
                    bf[0] = __float_as_uint(Vb[(ks * 8 + tig) * VSS + d0]);
                    bf[1] = __float_as_uint(Vb[(ks * 8 + tig + 4) * VSS + d0]);
                    mma_tf32(oacc[nj], af, bf);
                }
            }
            __syncwarp();
        }
    }

    // write O (divide by l, RN-round: operand of attnproj GEMM)
    {
        float li0 = 1.0f / l0, li1 = 1.0f / l1;
#pragma unroll
        for (int nj = 0; nj < 8; nj++) {
            int c = h * HD + nj * 8 + 2 * tig;
            *(float2*)&y[(size_t)(b * TDIM + row0) * CDIM + c] =
                make_float2(rtf(oacc[nj][0] * li0), rtf(oacc[nj][1] * li0));
            *(float2*)&y[(size_t)(b * TDIM + row1) * CDIM + c] =
                make_float2(rtf(oacc[nj][2] * li1), rtf(oacc[nj][3] * li1));
        }
    }

    // entropy: H_row = m + log(S) - W/S
    if (tig == 0) {
        hrow[warp * 16 + g]     = m0 + logf(l0) - w0 / l0;
        hrow[warp * 16 + g + 8] = m1 + logf(l1) - w1 / l1;
    }
    __syncthreads();
    if (tid == 0) {
        float tot = 0.f;
        for (int i = 0; i < 128; i++) tot += hrow[i];
        atomicAdd(&g_ent, tot);
    }
}

// ------------------------------------------------------------------
extern "C" void kernel_launch(void* const* d_in, const int* in_sizes, int n_in,
                              void* d_out, int out_size) {
    const float* x          = (const float*)d_in[0];
    const float* ln1_w      = (const float*)d_in[1];
    const float* ln1_b      = (const float*)d_in[2];
    const float* attn_w     = (const float*)d_in[3];
    const float* attn_b     = (const float*)d_in[4];
    const float* attnproj_w = (const float*)d_in[5];
    const float* attnproj_b = (const float*)d_in[6];
    const float* ln2_w      = (const float*)d_in[7];
    const float* ln2_b      = (const float*)d_in[8];
    const float* fc_w       = (const float*)d_in[9];
    const float* fc_b       = (const float*)d_in[10];
    const float* proj_w     = (const float*)d_in[11];
    const float* proj_b     = (const float*)d_in[12];
    float* out = (float*)d_out;

    float *p_h, *p_qkv, *p_y, *p_x1, *p_m, *p_wr;
    cudaGetSymbolAddress((void**)&p_h,   g_h);
    cudaGetSymbolAddress((void**)&p_qkv, g_qkv);
    cudaGetSymbolAddress((void**)&p_y,   g_y);
    cudaGetSymbolAddress((void**)&p_x1,  g_x1);
    cudaGetSymbolAddress((void**)&p_m,   g_m);
    cudaGetSymbolAddress((void**)&p_wr,  g_wr);

    static int gemm_smem = 4 * GBUF * 4;
    static int attn_smem = (2 * KB1 + 2 * VB1 + 128 * QS + 128) * 4;
    cudaFuncSetAttribute(gemm_tc,
                         cudaFuncAttributeMaxDynamicSharedMemorySize, gemm_smem);
    cudaFuncSetAttribute(flash_attn_tc,
                         cudaFuncAttributeMaxDynamicSharedMemorySize, attn_smem);

    zero_ent_kernel<<<1, 1>>>();

    // RN-round weights to tf32 once per launch
    round4_kernel<<<3145728 / 1024, 256>>>(attn_w,     p_wr + WR_ATTN,  3145728);
    round4_kernel<<<1048576 / 1024, 256>>>(attnproj_w, p_wr + WR_APROJ, 1048576);
    round4_kernel<<<4194304 / 1024, 256>>>(fc_w,       p_wr + WR_FC,    4194304);
    round4_kernel<<<4194304 / 1024, 256>>>(proj_w,     p_wr + WR_PROJ,  4194304);

    // h = LN1(x)  (RN tf32)
    ln_kernel<<<BT, 256>>>(x, ln1_w, ln1_b, p_h);

    // qkv = h @ attn_w^T + attn_b   (RN output -> attention operands)
    gemm_tc<<<dim3(QKVC / 128, BT / 128), 256, gemm_smem>>>(
        p_h, p_wr + WR_ATTN, attn_b, nullptr, p_qkv, BT, QKVC, CDIM, 0, 1);

    // attention (+entropy)
    flash_attn_tc<<<dim3(TDIM / 128, BH), 256, attn_smem>>>(p_qkv, p_y);

    // x1 = x + y @ attnproj_w^T + attnproj_b
    gemm_tc<<<dim3(CDIM / 128, BT / 128), 256, gemm_smem>>>(
        p_y, p_wr + WR_APROJ, attnproj_b, x, p_x1, BT, CDIM, CDIM, 0, 0);

    // h = LN2(x1)  (RN tf32)
    ln_kernel<<<BT, 256>>>(p_x1, ln2_w, ln2_b, p_h);

    // m = gelu(h @ fc_w^T + fc_b)   (RN output -> proj operand)
    gemm_tc<<<dim3(FFC / 128, BT / 128), 256, gemm_smem>>>(
        p_h, p_wr + WR_FC, fc_b, nullptr, p_m, BT, FFC, CDIM, 1, 1);

    // out = x1 + m @ proj_w^T + proj_b
    gemm_tc<<<dim3(CDIM / 128, BT / 128), 256, gemm_smem>>>(
        p_m, p_wr + WR_PROJ, proj_b, p_x1, out, BT, CDIM, FFC, 0, 0);

    // entropy scalar
    finalize_kernel<<<1, 1>>>(out, out_size);
}

// round 7
// speedup vs baseline: 10.1771x; 1.0433x over previous
#include <cuda_runtime.h>
#include <math.h>
#include <stdint.h>

// Problem constants
#define BATCH 2
#define TDIM 2048
#define CDIM 1024
#define HN 16
#define HD 64
#define BT (BATCH * TDIM)        // 4096 rows
#define BH (BATCH * HN)          // 32 batch-heads
#define QKVC (3 * CDIM)          // 3072
#define FFC (4 * CDIM)           // 4096

#define NEG_BIG (-1e30f)

// -------- scratch (static device globals; no allocation) ----------
__device__ float g_h[BT * CDIM];
__device__ float g_qkv[BT * QKVC];
__device__ float g_y[BT * CDIM];
__device__ float g_x1[BT * CDIM];
__device__ float g_m[BT * FFC];
__device__ float g_wr[12582912];   // RN-rounded weights: attn|attnproj|fc|proj
__device__ float g_ent;

#define WR_ATTN  0
#define WR_APROJ 3145728
#define WR_FC    4194304
#define WR_PROJ  8388608

// ------------------------------------------------------------------
__global__ void zero_ent_kernel() { g_ent = 0.0f; }

__global__ void finalize_kernel(float* out, int out_size) {
    if (out_size > BT * CDIM)
        out[BT * CDIM] = g_ent * (1.0f / (float)(BH * TDIM));
}

// -------- helpers -------------------------------------------------
__device__ __forceinline__ float rtf(float x) {   // round-to-nearest tf32
    uint32_t u; asm("cvt.rna.tf32.f32 %0, %1;" : "=r"(u) : "f"(x));
    return __uint_as_float(u);
}

__device__ __forceinline__ void cp16(void* s, const void* g) {
    unsigned sa = (unsigned)__cvta_generic_to_shared(s);
    asm volatile("cp.async.cg.shared.global [%0], [%1], 16;" :: "r"(sa), "l"(g));
}
#define CP_COMMIT() asm volatile("cp.async.commit_group;")
#define CP_WAIT0()  asm volatile("cp.async.wait_group 0;")

__device__ __forceinline__ void mma_tf32(float* c, const unsigned* a, const unsigned* b) {
    asm("mma.sync.aligned.m16n8k8.row.col.f32.tf32.tf32.f32 "
        "{%0,%1,%2,%3}, {%4,%5,%6,%7}, {%8,%9}, {%0,%1,%2,%3};"
        : "+f"(c[0]), "+f"(c[1]), "+f"(c[2]), "+f"(c[3])
        : "r"(a[0]), "r"(a[1]), "r"(a[2]), "r"(a[3]), "r"(b[0]), "r"(b[1]));
}

// -------- weight rounding: 4 independent float4 per thread (MLP=4)
__global__ void round4_kernel(const float* __restrict__ in,
                              float* __restrict__ out, int n) {
    int base = (blockIdx.x * blockDim.x + threadIdx.x) * 16;
    if (base + 16 <= n) {
        float4 a = *(const float4*)&in[base];
        float4 b = *(const float4*)&in[base + 4];
        float4 c = *(const float4*)&in[base + 8];
        float4 d = *(const float4*)&in[base + 12];
        a.x = rtf(a.x); a.y = rtf(a.y); a.z = rtf(a.z); a.w = rtf(a.w);
        b.x = rtf(b.x); b.y = rtf(b.y); b.z = rtf(b.z); b.w = rtf(b.w);
        c.x = rtf(c.x); c.y = rtf(c.y); c.z = rtf(c.z); c.w = rtf(c.w);
        d.x = rtf(d.x); d.y = rtf(d.y); d.z = rtf(d.z); d.w = rtf(d.w);
        *(float4*)&out[base]      = a;
        *(float4*)&out[base + 4]  = b;
        *(float4*)&out[base + 8]  = c;
        *(float4*)&out[base + 12] = d;
    }
}

// -------- LayerNorm: float4 path, two-level shuffle reduction -----
__global__ void ln_kernel(const float* __restrict__ x,
                          const float* __restrict__ w,
                          const float* __restrict__ b,
                          float* __restrict__ out) {
    int row = blockIdx.x;
    int tid = threadIdx.x;
    int lane = tid & 31, warp = tid >> 5;
    const float* xr = x + (size_t)row * CDIM;
    __shared__ float rs[8], rq[8];

    float4 v = *(const float4*)&xr[tid * 4];
    float lsum = v.x + v.y + v.z + v.w;
    float lsq  = v.x * v.x + v.y * v.y + v.z * v.z + v.w * v.w;
#pragma unroll
    for (int o = 16; o > 0; o >>= 1) {
        lsum += __shfl_xor_sync(0xFFFFFFFFu, lsum, o);
        lsq  += __shfl_xor_sync(0xFFFFFFFFu, lsq, o);
    }
    if (lane == 0) { rs[warp] = lsum; rq[warp] = lsq; }
    __syncthreads();
    float tsum, tsq;
    {
        float a = rs[lane & 7], c = rq[lane & 7];
#pragma unroll
        for (int o = 4; o > 0; o >>= 1) {
            a += __shfl_xor_sync(0xFFFFFFFFu, a, o);
            c += __shfl_xor_sync(0xFFFFFFFFu, c, o);
        }
        tsum = a; tsq = c;
    }
    float mean = tsum * (1.0f / CDIM);
    float var = tsq * (1.0f / CDIM) - mean * mean;
    float rstd = rsqrtf(var + 1e-5f);

    float4 wv = *(const float4*)&w[tid * 4];
    float4 bv = *(const float4*)&b[tid * 4];
    float4 o4;
    o4.x = rtf((v.x - mean) * rstd * wv.x + bv.x);
    o4.y = rtf((v.y - mean) * rstd * wv.y + bv.y);
    o4.z = rtf((v.z - mean) * rstd * wv.z + bv.z);
    o4.w = rtf((v.w - mean) * rstd * wv.w + bv.w);
    *(float4*)&out[(size_t)row * CDIM + tid * 4] = o4;
}

__device__ __forceinline__ float gelu_tanh(float x) {
    const float k0 = 0.7978845608028654f;
    const float k1 = 0.044715f;
    float u = k0 * (x + k1 * x * x * x);
    float t = __expf(2.0f * u);
    float th = (t - 1.0f) / (t + 1.0f);
    return 0.5f * x * (1.0f + th);
}

// -------- tf32 tensor-core GEMM: C = A[M,K]*W[N,K]^T + bias --------
// 128x128x32 tile, 256 threads, warp grid 2(m)x4(n), warp tile 64x32.
// cp.async double-buffered; 2 CTAs/SM for latency hiding.
#define GST 36
#define GBUF (128 * GST)

__global__ __launch_bounds__(256, 2)
void gemm_tc(const float* __restrict__ A, const float* __restrict__ W,
             const float* __restrict__ bias, const float* __restrict__ resid,
             float* __restrict__ C, int M, int N, int K, int act, int rnd) {
    extern __shared__ float sm[];
    float* As = sm;
    float* Ws = sm + 2 * GBUF;

    int tid = threadIdx.x;
    int warp = tid >> 5, lane = tid & 31;
    int wm = warp >> 2, wn = warp & 3;
    int g = lane >> 2, tig = lane & 3;
    int rowBase = blockIdx.y * 128, colBase = blockIdx.x * 128;
    const float* Ap = A + (size_t)rowBase * K;
    const float* Wp = W + (size_t)colBase * K;

    float acc[4][4][4];
#pragma unroll
    for (int i = 0; i < 4; i++)
#pragma unroll
        for (int j = 0; j < 4; j++)
#pragma unroll
            for (int p = 0; p < 4; p++) acc[i][j][p] = 0.f;

    int lr = tid >> 3;
    int lc = (tid & 7) * 4;

#pragma unroll
    for (int it = 0; it < 4; it++) {
        int r = lr + it * 32;
        cp16(&As[r * GST + lc], Ap + (size_t)r * K + lc);
        cp16(&Ws[r * GST + lc], Wp + (size_t)r * K + lc);
    }
    CP_COMMIT();

    int nt = K >> 5;
    for (int t = 0; t < nt; t++) {
        CP_WAIT0();
        __syncthreads();
        if (t + 1 < nt) {
            int kt = (t + 1) << 5;
            int nb = (t + 1) & 1;
#pragma unroll
            for (int it = 0; it < 4; it++) {
                int r = lr + it * 32;
                cp16(&As[nb * GBUF + r * GST + lc], Ap + (size_t)r * K + kt + lc);
                cp16(&Ws[nb * GBUF + r * GST + lc], Wp + (size_t)r * K + kt + lc);
            }
            CP_COMMIT();
        }
        const float* Ab = As + (t & 1) * GBUF;
        const float* Wb = Ws + (t & 1) * GBUF;
#pragma unroll
        for (int ks = 0; ks < 4; ks++) {
            unsigned af[4][4], bf[4][2];
#pragma unroll
            for (int mi = 0; mi < 4; mi++) {
                int r0 = wm * 64 + mi * 16 + g;
                af[mi][0] = __float_as_uint(Ab[r0 * GST + ks * 8 + tig]);
                af[mi][1] = __float_as_uint(Ab[(r0 + 8) * GST + ks * 8 + tig]);
                af[mi][2] = __float_as_uint(Ab[r0 * GST + ks * 8 + tig + 4]);
                af[mi][3] = __float_as_uint(Ab[(r0 + 8) * GST + ks * 8 + tig + 4]);
            }
#pragma unroll
            for (int nj = 0; nj < 4; nj++) {
                int c0 = wn * 32 + nj * 8 + g;
                bf[nj][0] = __float_as_uint(Wb[c0 * GST + ks * 8 + tig]);
                bf[nj][1] = __float_as_uint(Wb[c0 * GST + ks * 8 + tig + 4]);
            }
#pragma unroll
            for (int mi = 0; mi < 4; mi++)
#pragma unroll
                for (int nj = 0; nj < 4; nj++)
                    mma_tf32(acc[mi][nj], af[mi], bf[nj]);
        }
        __syncthreads();
    }

    // epilogue
#pragma unroll
    for (int mi = 0; mi < 4; mi++) {
#pragma unroll
        for (int h2 = 0; h2 < 2; h2++) {
            int r = rowBase + wm * 64 + mi * 16 + g + h2 * 8;
            float* crow = C + (size_t)r * N;
            const float* rrow = resid ? resid + (size_t)r * N : nullptr;
#pragma unroll
            for (int nj = 0; nj < 4; nj++) {
                int c = colBase + wn * 32 + nj * 8 + 2 * tig;
                float v0 = acc[mi][nj][h2 * 2]     + bias[c];
                float v1 = acc[mi][nj][h2 * 2 + 1] + bias[c + 1];
                if (act == 1) { v0 = gelu_tanh(v0); v1 = gelu_tanh(v1); }
                if (rrow) { v0 += rrow[c]; v1 += rrow[c + 1]; }
                if (rnd) { v0 = rtf(v0); v1 = rtf(v1); }
                *(float2*)&crow[c] = make_float2(v0, v1);
            }
        }
    }
}

// -------- Flash attention: 128q x 64k tiles, per-warp pipeline -----
#define QS 68
#define VSS 72
#define KB1 (64 * QS)
#define VB1 (64 * VSS)

__global__ __launch_bounds__(256)
void flash_attn_tc(const float* __restrict__ qkv, float* __restrict__ y) {
    extern __shared__ float smf[];
    float* Ks = smf;                  // [2][64][68]
    float* Vs = Ks + 2 * KB1;         // [2][64][72]
    float* Ps = Vs + 2 * VB1;         // [128][68]  Q staging, then P probs
    float* hrow = Ps + 128 * QS;      // [128]

    int tid = threadIdx.x;
    int warp = tid >> 5, lane = tid & 31;
    int g = lane >> 2, tig = lane & 3;
    int qt = (TDIM / 128 - 1) - blockIdx.x;   // long tiles first
    int bh = blockIdx.y;
    int b = bh >> 4, h = bh & 15;
    int qb = qt * 128;
    const float* base = qkv + (size_t)b * TDIM * QKVC + h * HD;

    // prefetch Q (128x64 -> Ps) + K0 + V0
#pragma unroll
    for (int i = 0; i < 8; i++) {
        int ch = tid + i * 256; int r = ch >> 4; int c = (ch & 15) * 4;
        cp16(&Ps[r * QS + c], &base[(size_t)(qb + r) * QKVC + c]);
    }
#pragma unroll
    for (int i = 0; i < 4; i++) {
        int ch = tid + i * 256; int r = ch >> 4; int c = (ch & 15) * 4;
        cp16(&Ks[r * QS + c], &base[(size_t)r * QKVC + CDIM + c]);
        cp16(&Vs[r * VSS + c], &base[(size_t)r * QKVC + 2 * CDIM + c]);
    }
    CP_COMMIT();
    CP_WAIT0();
    __syncthreads();

    // hoist Q fragments (warp's 16 rows x 64 d)
    int r0l = warp * 16 + g;
    unsigned qf[8][4];
#pragma unroll
    for (int ks = 0; ks < 8; ks++) {
        qf[ks][0] = __float_as_uint(Ps[r0l * QS + ks * 8 + tig]);
        qf[ks][1] = __float_as_uint(Ps[(r0l + 8) * QS + ks * 8 + tig]);
        qf[ks][2] = __float_as_uint(Ps[r0l * QS + ks * 8 + tig + 4]);
        qf[ks][3] = __float_as_uint(Ps[(r0l + 8) * QS + ks * 8 + tig + 4]);
    }

    float m0 = NEG_BIG, m1 = NEG_BIG, l0 = 0.f, l1 = 0.f, w0 = 0.f, w1 = 0.f;
    float oacc[8][4];
#pragma unroll
    for (int nj = 0; nj < 8; nj++)
#pragma unroll
        for (int p = 0; p < 4; p++) oacc[nj][p] = 0.f;

    int row0 = qb + warp * 16 + g, row1 = row0 + 8;
    int ni = 2 * qt + 2;

    for (int i = 0; i < ni; i++) {
        CP_WAIT0();
        __syncthreads();
        if (i + 1 < ni) {
            int nb = (i + 1) & 1, kb2 = (i + 1) * 64;
#pragma unroll
            for (int it = 0; it < 4; it++) {
                int ch = tid + it * 256; int r = ch >> 4; int c = (ch & 15) * 4;
                cp16(&Ks[nb * KB1 + r * QS + c],
                     &base[(size_t)(kb2 + r) * QKVC + CDIM + c]);
                cp16(&Vs[nb * VB1 + r * VSS + c],
                     &base[(size_t)(kb2 + r) * QKVC + 2 * CDIM + c]);
            }
            CP_COMMIT();
        }
        int kb = i * 64;
        if (qb + warp * 16 + 15 >= kb) {   // warp has unmasked rows here
            const float* Kb = Ks + (i & 1) * KB1;
            const float* Vb = Vs + (i & 1) * VB1;

            // ---- S = Q K^T (registers) ----
            float sacc[8][4];
#pragma unroll
            for (int nj = 0; nj < 8; nj++)
#pragma unroll
                for (int p = 0; p < 4; p++) sacc[nj][p] = 0.f;
#pragma unroll
            for (int ks = 0; ks < 8; ks++) {
#pragma unroll
                for (int nj = 0; nj < 8; nj++) {
                    int c0 = nj * 8 + g;
                    unsigned bf[2];
                    bf[0] = __float_as_uint(Kb[c0 * QS + ks * 8 + tig]);
                    bf[1] = __float_as_uint(Kb[c0 * QS + ks * 8 + tig + 4]);
                    mma_tf32(sacc[nj], qf[ks], bf);
                }
            }

            // ---- scale + mask + row max ----
            float mx0 = NEG_BIG, mx1 = NEG_BIG;
#pragma unroll
            for (int nj = 0; nj < 8; nj++) {
                int cg = kb + nj * 8 + 2 * tig;
                float s0 = sacc[nj][0] * 0.125f;
                float s1 = sacc[nj][1] * 0.125f;
                float s2 = sacc[nj][2] * 0.125f;
                float s3 = sacc[nj][3] * 0.125f;
                if (cg > row0) s0 = NEG_BIG;
                if (cg + 1 > row0) s1 = NEG_BIG;
                if (cg > row1) s2 = NEG_BIG;
                if (cg + 1 > row1) s3 = NEG_BIG;
                sacc[nj][0] = s0; sacc[nj][1] = s1;
                sacc[nj][2] = s2; sacc[nj][3] = s3;
                mx0 = fmaxf(mx0, fmaxf(s0, s1));
                mx1 = fmaxf(mx1, fmaxf(s2, s3));
            }
            mx0 = fmaxf(mx0, __shfl_xor_sync(0xFFFFFFFFu, mx0, 1));
            mx0 = fmaxf(mx0, __shfl_xor_sync(0xFFFFFFFFu, mx0, 2));
            mx1 = fmaxf(mx1, __shfl_xor_sync(0xFFFFFFFFu, mx1, 1));
            mx1 = fmaxf(mx1, __shfl_xor_sync(0xFFFFFFFFu, mx1, 2));
            float mn0 = fmaxf(m0, mx0), mn1 = fmaxf(m1, mx1);

            // ---- exp + sums + write P ----
            float se0 = 0.f, se1 = 0.f, sw0 = 0.f, sw1 = 0.f;
#pragma unroll
            for (int nj = 0; nj < 8; nj++) {
                float s0 = sacc[nj][0], s1 = sacc[nj][1];
                float s2 = sacc[nj][2], s3 = sacc[nj][3];
                float e0 = __expf(s0 - mn0), e1 = __expf(s1 - mn0);
                float e2 = __expf(s2 - mn1), e3 = __expf(s3 - mn1);
                se0 += e0 + e1; sw0 += e0 * s0 + e1 * s1;
                se1 += e2 + e3; sw1 += e2 * s2 + e3 * s3;
                int c0 = nj * 8 + 2 * tig;
                *(float2*)&Ps[(warp * 16 + g) * QS + c0] =
                    make_float2(rtf(e0), rtf(e1));
                *(float2*)&Ps[(warp * 16 + g + 8) * QS + c0] =
                    make_float2(rtf(e2), rtf(e3));
            }
            se0 += __shfl_xor_sync(0xFFFFFFFFu, se0, 1);
            se0 += __shfl_xor_sync(0xFFFFFFFFu, se0, 2);
            sw0 += __shfl_xor_sync(0xFFFFFFFFu, sw0, 1);
            sw0 += __shfl_xor_sync(0xFFFFFFFFu, sw0, 2);
            se1 += __shfl_xor_sync(0xFFFFFFFFu, se1, 1);
            se1 += __shfl_xor_sync(0xFFFFFFFFu, se1, 2);
            sw1 += __shfl_xor_sync(0xFFFFFFFFu, sw1, 1);
            sw1 += __shfl_xor_sync(0xFFFFFFFFu, sw1, 2);

            float c0f = __expf(m0 - mn0), c1f = __expf(m1 - mn1);
            l0 = l0 * c0f + se0; w0 = w0 * c0f + sw0; m0 = mn0;
            l1 = l1 * c1f + se1; w1 = w1 * c1f + sw1; m1 = mn1;
#pragma unroll
            for (int nj = 0; nj < 8; nj++) {
                oacc[nj][0] *= c0f; oacc[nj][1] *= c0f;
                oacc[nj][2] *= c1f; oacc[nj][3] *= c1f;
            }
            __syncwarp();

            // ---- O += P V ----
#pragma unroll
            for (int ks = 0; ks < 8; ks++) {
                unsigned af[4];
                af[0] = __float_as_uint(Ps[r0l * QS + ks * 8 + tig]);
                af[1] = __float_as_uint(Ps[(r0l + 8) * QS + ks * 8 + tig]);
                af[2] = __float_as_uint(Ps[r0l * QS + ks * 8 + tig + 4]);
                af[3] = __float_as_uint(Ps[(r0l + 8) * QS + ks * 8 + tig + 4]);
#pragma unroll
                for (int nj = 0; nj < 8; nj++) {
                    int d0 = nj * 8 + g;
                    unsigned bf[2];
                    bf[0] = __float_as_uint(Vb[(ks * 8 + tig) * VSS + d0]);
                    bf[1] = __float_as_uint(Vb[(ks * 8 + tig + 4) * VSS + d0]);
                    mma_tf32(oacc[nj], af, bf);
                }
            }
            __syncwarp();
        }
    }

    // write O (divide by l, RN-round: operand of attnproj GEMM)
    {
        float li0 = 1.0f / l0, li1 = 1.0f / l1;
#pragma unroll
        for (int nj = 0; nj < 8; nj++) {
            int c = h * HD + nj * 8 + 2 * tig;
            *(float2*)&y[(size_t)(b * TDIM + row0) * CDIM + c] =
                make_float2(rtf(oacc[nj][0] * li0), rtf(oacc[nj][1] * li0));
            *(float2*)&y[(size_t)(b * TDIM + row1) * CDIM + c] =
                make_float2(rtf(oacc[nj][2] * li1), rtf(oacc[nj][3] * li1));
        }
    }

    // entropy: H_row = m + log(S) - W/S
    if (tig == 0) {
        hrow[warp * 16 + g]     = m0 + logf(l0) - w0 / l0;
        hrow[warp * 16 + g + 8] = m1 + logf(l1) - w1 / l1;
    }
    __syncthreads();
    if (tid == 0) {
        float tot = 0.f;
        for (int i = 0; i < 128; i++) tot += hrow[i];
        atomicAdd(&g_ent, tot);
    }
}

// ------------------------------------------------------------------
extern "C" void kernel_launch(void* const* d_in, const int* in_sizes, int n_in,
                              void* d_out, int out_size) {
    const float* x          = (const float*)d_in[0];
    const float* ln1_w      = (const float*)d_in[1];
    const float* ln1_b      = (const float*)d_in[2];
    const float* attn_w     = (const float*)d_in[3];
    const float* attn_b     = (const float*)d_in[4];
    const float* attnproj_w = (const float*)d_in[5];
    const float* attnproj_b = (const float*)d_in[6];
    const float* ln2_w      = (const float*)d_in[7];
    const float* ln2_b      = (const float*)d_in[8];
    const float* fc_w       = (const float*)d_in[9];
    const float* fc_b       = (const float*)d_in[10];
    const float* proj_w     = (const float*)d_in[11];
    const float* proj_b     = (const float*)d_in[12];
    float* out = (float*)d_out;

    float *p_h, *p_qkv, *p_y, *p_x1, *p_m, *p_wr;
    cudaGetSymbolAddress((void**)&p_h,   g_h);
    cudaGetSymbolAddress((void**)&p_qkv, g_qkv);
    cudaGetSymbolAddress((void**)&p_y,   g_y);
    cudaGetSymbolAddress((void**)&p_x1,  g_x1);
    cudaGetSymbolAddress((void**)&p_m,   g_m);
    cudaGetSymbolAddress((void**)&p_wr,  g_wr);

    static int gemm_smem = 4 * GBUF * 4;
    static int attn_smem = (2 * KB1 + 2 * VB1 + 128 * QS + 128) * 4;
    cudaFuncSetAttribute(gemm_tc,
                         cudaFuncAttributeMaxDynamicSharedMemorySize, gemm_smem);
    cudaFuncSetAttribute(flash_attn_tc,
                         cudaFuncAttributeMaxDynamicSharedMemorySize, attn_smem);

    zero_ent_kernel<<<1, 1>>>();

    // RN-round weights to tf32 once per launch (16 floats per thread)
    round4_kernel<<<3145728 / (16 * 256), 256>>>(attn_w,     p_wr + WR_ATTN,  3145728);
    round4_kernel<<<1048576 / (16 * 256), 256>>>(attnproj_w, p_wr + WR_APROJ, 1048576);
    round4_kernel<<<4194304 / (16 * 256), 256>>>(fc_w,       p_wr + WR_FC,    4194304);
    round4_kernel<<<4194304 / (16 * 256), 256>>>(proj_w,     p_wr + WR_PROJ,  4194304);

    // h = LN1(x)  (RN tf32)
    ln_kernel<<<BT, 256>>>(x, ln1_w, ln1_b, p_h);

    // qkv = h @ attn_w^T + attn_b
    gemm_tc<<<dim3(QKVC / 128, BT / 128), 256, gemm_smem>>>(
        p_h, p_wr + WR_ATTN, attn_b, nullptr, p_qkv, BT, QKVC, CDIM, 0, 1);

    // attention (+entropy)
    flash_attn_tc<<<dim3(TDIM / 128, BH), 256, attn_smem>>>(p_qkv, p_y);

    // x1 = x + y @ attnproj_w^T + attnproj_b
    gemm_tc<<<dim3(CDIM / 128, BT / 128), 256, gemm_smem>>>(
        p_y, p_wr + WR_APROJ, attnproj_b, x, p_x1, BT, CDIM, CDIM, 0, 0);

    // h = LN2(x1)  (RN tf32)
    ln_kernel<<<BT, 256>>>(p_x1, ln2_w, ln2_b, p_h);

    // m = gelu(h @ fc_w^T + fc_b)
    gemm_tc<<<dim3(FFC / 128, BT / 128), 256, gemm_smem>>>(
        p_h, p_wr + WR_FC, fc_b, nullptr, p_m, BT, FFC, CDIM, 1, 1);

    // out = x1 + m @ proj_w^T + proj_b
    gemm_tc<<<dim3(CDIM / 128, BT / 128), 256, gemm_smem>>>(
        p_m, p_wr + WR_PROJ, proj_b, p_x1, out, BT, CDIM, FFC, 0, 0);

    // entropy scalar
    finalize_kernel<<<1, 1>>>(out, out_size);
}

// round 9
// speedup vs baseline: 10.2782x; 1.0099x over previous
#include <cuda_runtime.h>
#include <math.h>
#include <stdint.h>

// Problem constants
#define BATCH 2
#define TDIM 2048
#define CDIM 1024
#define HN 16
#define HD 64
#define BT (BATCH * TDIM)        // 4096 rows
#define BH (BATCH * HN)          // 32 batch-heads
#define QKVC (3 * CDIM)          // 3072
#define FFC (4 * CDIM)           // 4096

#define NEG_BIG (-1e30f)

// -------- scratch (static device globals; no allocation) ----------
__device__ float g_h[BT * CDIM];
__device__ float g_qkv[BT * QKVC];
__device__ float g_y[BT * CDIM];
__device__ float g_x1[BT * CDIM];
__device__ float g_m[BT * FFC];
__device__ float g_wr[12582912];   // RN-rounded weights: attn|attnproj|fc|proj
__device__ float g_ent;

#define WR_ATTN  0
#define WR_APROJ 3145728
#define WR_FC    4194304
#define WR_PROJ  8388608

// ------------------------------------------------------------------
__global__ void zero_ent_kernel() { g_ent = 0.0f; }

__global__ void finalize_kernel(float* out, int out_size) {
    if (out_size > BT * CDIM)
        out[BT * CDIM] = g_ent * (1.0f / (float)(BH * TDIM));
}

// -------- helpers -------------------------------------------------
__device__ __forceinline__ float rtf(float x) {   // round-to-nearest tf32
    uint32_t u; asm("cvt.rna.tf32.f32 %0, %1;" : "=r"(u) : "f"(x));
    return __uint_as_float(u);
}

__device__ __forceinline__ void cp16(void* s, const void* g) {
    unsigned sa = (unsigned)__cvta_generic_to_shared(s);
    asm volatile("cp.async.cg.shared.global [%0], [%1], 16;" :: "r"(sa), "l"(g));
}
#define CP_COMMIT() asm volatile("cp.async.commit_group;")
#define CP_WAIT0()  asm volatile("cp.async.wait_group 0;")

__device__ __forceinline__ void mma_tf32(float* c, const unsigned* a, const unsigned* b) {
    asm("mma.sync.aligned.m16n8k8.row.col.f32.tf32.tf32.f32 "
        "{%0,%1,%2,%3}, {%4,%5,%6,%7}, {%8,%9}, {%0,%1,%2,%3};"
        : "+f"(c[0]), "+f"(c[1]), "+f"(c[2]), "+f"(c[3])
        : "r"(a[0]), "r"(a[1]), "r"(a[2]), "r"(a[3]), "r"(b[0]), "r"(b[1]));
}

// -------- weight rounding (4 floats/thread — measured fastest) ----
__global__ void round4_kernel(const float* __restrict__ in,
                              float* __restrict__ out, int n) {
    int i = (blockIdx.x * blockDim.x + threadIdx.x) * 4;
    if (i < n) {
        float4 v = *(const float4*)&in[i];
        v.x = rtf(v.x); v.y = rtf(v.y); v.z = rtf(v.z); v.w = rtf(v.w);
        *(float4*)&out[i] = v;
    }
}

// -------- LayerNorm: float4 path, two-level shuffle reduction -----
__global__ void ln_kernel(const float* __restrict__ x,
                          const float* __restrict__ w,
                          const float* __restrict__ b,
                          float* __restrict__ out) {
    int row = blockIdx.x;
    int tid = threadIdx.x;
    int lane = tid & 31, warp = tid >> 5;
    const float* xr = x + (size_t)row * CDIM;
    __shared__ float rs[8], rq[8];

    float4 v = *(const float4*)&xr[tid * 4];
    float lsum = v.x + v.y + v.z + v.w;
    float lsq  = v.x * v.x + v.y * v.y + v.z * v.z + v.w * v.w;
#pragma unroll
    for (int o = 16; o > 0; o >>= 1) {
        lsum += __shfl_xor_sync(0xFFFFFFFFu, lsum, o);
        lsq  += __shfl_xor_sync(0xFFFFFFFFu, lsq, o);
    }
    if (lane == 0) { rs[warp] = lsum; rq[warp] = lsq; }
    __syncthreads();
    float tsum, tsq;
    {
        float a = rs[lane & 7], c = rq[lane & 7];
#pragma unroll
        for (int o = 4; o > 0; o >>= 1) {
            a += __shfl_xor_sync(0xFFFFFFFFu, a, o);
            c += __shfl_xor_sync(0xFFFFFFFFu, c, o);
        }
        tsum = a; tsq = c;
    }
    float mean = tsum * (1.0f / CDIM);
    float var = tsq * (1.0f / CDIM) - mean * mean;
    float rstd = rsqrtf(var + 1e-5f);

    float4 wv = *(const float4*)&w[tid * 4];
    float4 bv = *(const float4*)&b[tid * 4];
    float4 o4;
    o4.x = rtf((v.x - mean) * rstd * wv.x + bv.x);
    o4.y = rtf((v.y - mean) * rstd * wv.y + bv.y);
    o4.z = rtf((v.z - mean) * rstd * wv.z + bv.z);
    o4.w = rtf((v.w - mean) * rstd * wv.w + bv.w);
    *(float4*)&out[(size_t)row * CDIM + tid * 4] = o4;
}

__device__ __forceinline__ float gelu_tanh(float x) {
    const float k0 = 0.7978845608028654f;
    const float k1 = 0.044715f;
    float u = k0 * (x + k1 * x * x * x);
    float t = __expf(2.0f * u);
    float th = (t - 1.0f) / (t + 1.0f);
    return 0.5f * x * (1.0f + th);
}

// -------- tf32 tensor-core GEMM: C = A[M,K]*W[N,K]^T + bias --------
// 128x128x32 tile, 256 threads, warp grid 2(m)x4(n), warp tile 64x32.
// 3-stage cp.async pipeline, ONE __syncthreads per k-tile, 2 CTAs/SM.
#define GST 36
#define GBUF (128 * GST)

__global__ __launch_bounds__(256, 2)
void gemm_tc(const float* __restrict__ A, const float* __restrict__ W,
             const float* __restrict__ bias, const float* __restrict__ resid,
             float* __restrict__ C, int M, int N, int K, int act, int rnd) {
    extern __shared__ float sm[];
    float* As = sm;                  // [3][128][36]
    float* Ws = sm + 3 * GBUF;       // [3][128][36]

    int tid = threadIdx.x;
    int warp = tid >> 5, lane = tid & 31;
    int wm = warp >> 2, wn = warp & 3;
    int g = lane >> 2, tig = lane & 3;
    int rowBase = blockIdx.y * 128, colBase = blockIdx.x * 128;
    const float* Ap = A + (size_t)rowBase * K;
    const float* Wp = W + (size_t)colBase * K;

    float acc[4][4][4];
#pragma unroll
    for (int i = 0; i < 4; i++)
#pragma unroll
        for (int j = 0; j < 4; j++)
#pragma unroll
            for (int p = 0; p < 4; p++) acc[i][j][p] = 0.f;

    int lr = tid >> 3;
    int lc = (tid & 7) * 4;

    // prologue: stage tiles 0 and 1
#pragma unroll
    for (int pt = 0; pt < 2; pt++) {
        int kt = pt << 5;
#pragma unroll
        for (int it = 0; it < 4; it++) {
            int r = lr + it * 32;
            cp16(&As[pt * GBUF + r * GST + lc], Ap + (size_t)r * K + kt + lc);
            cp16(&Ws[pt * GBUF + r * GST + lc], Wp + (size_t)r * K + kt + lc);
        }
        CP_COMMIT();
    }

    int nt = K >> 5;
    int buf = 0;
    for (int t = 0; t < nt; t++) {
        if (t == nt - 1) asm volatile("cp.async.wait_group 0;" ::: "memory");
        else             asm volatile("cp.async.wait_group 1;" ::: "memory");
        __syncthreads();
        if (t + 2 < nt) {
            int kt = (t + 2) << 5;
            int nb = buf >= 1 ? buf - 1 : buf + 2;   // (t+2)%3
#pragma unroll
            for (int it = 0; it < 4; it++) {
                int r = lr + it * 32;
                cp16(&As[nb * GBUF + r * GST + lc], Ap + (size_t)r * K + kt + lc);
                cp16(&Ws[nb * GBUF + r * GST + lc], Wp + (size_t)r * K + kt + lc);
            }
            CP_COMMIT();
        }
        const float* Ab = As + buf * GBUF;
        const float* Wb = Ws + buf * GBUF;
#pragma unroll
        for (int ks = 0; ks < 4; ks++) {
            unsigned af[4][4], bf[4][2];
#pragma unroll
            for (int mi = 0; mi < 4; mi++) {
                int r0 = wm * 64 + mi * 16 + g;
                af[mi][0] = __float_as_uint(Ab[r0 * GST + ks * 8 + tig]);
                af[mi][1] = __float_as_uint(Ab[(r0 + 8) * GST + ks * 8 + tig]);
                af[mi][2] = __float_as_uint(Ab[r0 * GST + ks * 8 + tig + 4]);
                af[mi][3] = __float_as_uint(Ab[(r0 + 8) * GST + ks * 8 + tig + 4]);
            }
#pragma unroll
            for (int nj = 0; nj < 4; nj++) {
                int c0 = wn * 32 + nj * 8 + g;
                bf[nj][0] = __float_as_uint(Wb[c0 * GST + ks * 8 + tig]);
                bf[nj][1] = __float_as_uint(Wb[c0 * GST + ks * 8 + tig + 4]);
            }
#pragma unroll
            for (int mi = 0; mi < 4; mi++)
#pragma unroll
                for (int nj = 0; nj < 4; nj++)
                    mma_tf32(acc[mi][nj], af[mi], bf[nj]);
        }
        buf = buf < 2 ? buf + 1 : 0;
    }

    // epilogue
#pragma unroll
    for (int mi = 0; mi < 4; mi++) {
#pragma unroll
        for (int h2 = 0; h2 < 2; h2++) {
            int r = rowBase + wm * 64 + mi * 16 + g + h2 * 8;
            float* crow = C + (size_t)r * N;
            const float* rrow = resid ? resid + (size_t)r * N : nullptr;
#pragma unroll
            for (int nj = 0; nj < 4; nj++) {
                int c = colBase + wn * 32 + nj * 8 + 2 * tig;
                float v0 = acc[mi][nj][h2 * 2]     + bias[c];
                float v1 = acc[mi][nj][h2 * 2 + 1] + bias[c + 1];
                if (act == 1) { v0 = gelu_tanh(v0); v1 = gelu_tanh(v1); }
                if (rrow) { v0 += rrow[c]; v1 += rrow[c + 1]; }
                if (rnd) { v0 = rtf(v0); v1 = rtf(v1); }
                *(float2*)&crow[c] = make_float2(v0, v1);
            }
        }
    }
}

// -------- Flash attention: 128q x 64k tiles, per-warp pipeline -----
// 2 CTAs/SM (smem 107KB x2 = 214KB <= 228KB).
#define QS 68
#define VSS 72
#define KB1 (64 * QS)
#define VB1 (64 * VSS)

__global__ __launch_bounds__(256, 2)
void flash_attn_tc(const float* __restrict__ qkv, float* __restrict__ y) {
    extern __shared__ float smf[];
    float* Ks = smf;                  // [2][64][68]
    float* Vs = Ks + 2 * KB1;         // [2][64][72]
    float* Ps = Vs + 2 * VB1;         // [128][68]  Q staging, then P probs
    float* hrow = Ps + 128 * QS;      // [128]

    int tid = threadIdx.x;
    int warp = tid >> 5, lane = tid & 31;
    int g = lane >> 2, tig = lane & 3;
    int qt = (TDIM / 128 - 1) - blockIdx.x;   // long tiles first
    int bh = blockIdx.y;
    int b = bh >> 4, h = bh & 15;
    int qb = qt * 128;
    const float* base = qkv + (size_t)b * TDIM * QKVC + h * HD;

    // prefetch Q (128x64 -> Ps) + K0 + V0
#pragma unroll
    for (int i = 0; i < 8; i++) {
        int ch = tid + i * 256; int r = ch >> 4; int c = (ch & 15) * 4;
        cp16(&Ps[r * QS + c], &base[(size_t)(qb + r) * QKVC + c]);
    }
#pragma unroll
    for (int i = 0; i < 4; i++) {
        int ch = tid + i * 256; int r = ch >> 4; int c = (ch & 15) * 4;
        cp16(&Ks[r * QS + c], &base[(size_t)r * QKVC + CDIM + c]);
        cp16(&Vs[r * VSS + c], &base[(size_t)r * QKVC + 2 * CDIM + c]);
    }
    CP_COMMIT();
    CP_WAIT0();
    __syncthreads();

    // hoist Q fragments (warp's 16 rows x 64 d)
    int r0l = warp * 16 + g;
    unsigned qf[8][4];
#pragma unroll
    for (int ks = 0; ks < 8; ks++) {
        qf[ks][0] = __float_as_uint(Ps[r0l * QS + ks * 8 + tig]);
        qf[ks][1] = __float_as_uint(Ps[(r0l + 8) * QS + ks * 8 + tig]);
        qf[ks][2] = __float_as_uint(Ps[r0l * QS + ks * 8 + tig + 4]);
        qf[ks][3] = __float_as_uint(Ps[(r0l + 8) * QS + ks * 8 + tig + 4]);
    }

    float m0 = NEG_BIG, m1 = NEG_BIG, l0 = 0.f, l1 = 0.f, w0 = 0.f, w1 = 0.f;
    float oacc[8][4];
#pragma unroll
    for (int nj = 0; nj < 8; nj++)
#pragma unroll
        for (int p = 0; p < 4; p++) oacc[nj][p] = 0.f;

    int row0 = qb + warp * 16 + g, row1 = row0 + 8;
    int ni = 2 * qt + 2;

    for (int i = 0; i < ni; i++) {
        CP_WAIT0();
        __syncthreads();
        if (i + 1 < ni) {
            int nb = (i + 1) & 1, kb2 = (i + 1) * 64;
#pragma unroll
            for (int it = 0; it < 4; it++) {
                int ch = tid + it * 256; int r = ch >> 4; int c = (ch & 15) * 4;
                cp16(&Ks[nb * KB1 + r * QS + c],
                     &base[(size_t)(kb2 + r) * QKVC + CDIM + c]);
                cp16(&Vs[nb * VB1 + r * VSS + c],
                     &base[(size_t)(kb2 + r) * QKVC + 2 * CDIM + c]);
            }
            CP_COMMIT();
        }
        int kb = i * 64;
        if (qb + warp * 16 + 15 >= kb) {   // warp has unmasked rows here
            const float* Kb = Ks + (i & 1) * KB1;
            const float* Vb = Vs + (i & 1) * VB1;

            // ---- S = Q K^T (registers) ----
            float sacc[8][4];
#pragma unroll
            for (int nj = 0; nj < 8; nj++)
#pragma unroll
                for (int p = 0; p < 4; p++) sacc[nj][p] = 0.f;
#pragma unroll
            for (int ks = 0; ks < 8; ks++) {
#pragma unroll
                for (int nj = 0; nj < 8; nj++) {
                    int c0 = nj * 8 + g;
                    unsigned bf[2];
                    bf[0] = __float_as_uint(Kb[c0 * QS + ks * 8 + tig]);
                    bf[1] = __float_as_uint(Kb[c0 * QS + ks * 8 + tig + 4]);
                    mma_tf32(sacc[nj], qf[ks], bf);
                }
            }

            // ---- scale + mask + row max ----
            float mx0 = NEG_BIG, mx1 = NEG_BIG;
#pragma unroll
            for (int nj = 0; nj < 8; nj++) {
                int cg = kb + nj * 8 + 2 * tig;
                float s0 = sacc[nj][0] * 0.125f;
                float s1 = sacc[nj][1] * 0.125f;
                float s2 = sacc[nj][2] * 0.125f;
                float s3 = sacc[nj][3] * 0.125f;
                if (cg > row0) s0 = NEG_BIG;
                if (cg + 1 > row0) s1 = NEG_BIG;
                if (cg > row1) s2 = NEG_BIG;
                if (cg + 1 > row1) s3 = NEG_BIG;
                sacc[nj][0] = s0; sacc[nj][1] = s1;
                sacc[nj][2] = s2; sacc[nj][3] = s3;
                mx0 = fmaxf(mx0, fmaxf(s0, s1));
                mx1 = fmaxf(mx1, fmaxf(s2, s3));
            }
            mx0 = fmaxf(mx0, __shfl_xor_sync(0xFFFFFFFFu, mx0, 1));
            mx0 = fmaxf(mx0, __shfl_xor_sync(0xFFFFFFFFu, mx0, 2));
            mx1 = fmaxf(mx1, __shfl_xor_sync(0xFFFFFFFFu, mx1, 1));
            mx1 = fmaxf(mx1, __shfl_xor_sync(0xFFFFFFFFu, mx1, 2));
            float mn0 = fmaxf(m0, mx0), mn1 = fmaxf(m1, mx1);

            // ---- exp + sums + write P ----
            float se0 = 0.f, se1 = 0.f, sw0 = 0.f, sw1 = 0.f;
#pragma unroll
            for (int nj = 0; nj < 8; nj++) {
                float s0 = sacc[nj][0], s1 = sacc[nj][1];
                float s2 = sacc[nj][2], s3 = sacc[nj][3];
                float e0 = __expf(s0 - mn0), e1 = __expf(s1 - mn0);
                float e2 = __expf(s2 - mn1), e3 = __expf(s3 - mn1);
                se0 += e0 + e1; sw0 += e0 * s0 + e1 * s1;
                se1 += e2 + e3; sw1 += e2 * s2 + e3 * s3;
                int c0 = nj * 8 + 2 * tig;
                *(float2*)&Ps[(warp * 16 + g) * QS + c0] =
                    make_float2(rtf(e0), rtf(e1));
                *(float2*)&Ps[(warp * 16 + g + 8) * QS + c0] =
                    make_float2(rtf(e2), rtf(e3));
            }
            se0 += __shfl_xor_sync(0xFFFFFFFFu, se0, 1);
            se0 += __shfl_xor_sync(0xFFFFFFFFu, se0, 2);
            sw0 += __shfl_xor_sync(0xFFFFFFFFu, sw0, 1);
            sw0 += __shfl_xor_sync(0xFFFFFFFFu, sw0, 2);
            se1 += __shfl_xor_sync(0xFFFFFFFFu, se1, 1);
            se1 += __shfl_xor_sync(0xFFFFFFFFu, se1, 2);
            sw1 += __shfl_xor_sync(0xFFFFFFFFu, sw1, 1);
            sw1 += __shfl_xor_sync(0xFFFFFFFFu, sw1, 2);

            float c0f = __expf(m0 - mn0), c1f = __expf(m1 - mn1);
            l0 = l0 * c0f + se0; w0 = w0 * c0f + sw0; m0 = mn0;
            l1 = l1 * c1f + se1; w1 = w1 * c1f + sw1; m1 = mn1;
#pragma unroll
            for (int nj = 0; nj < 8; nj++) {
                oacc[nj][0] *= c0f; oacc[nj][1] *= c0f;
                oacc[nj][2] *= c1f; oacc[nj][3] *= c1f;
            }
            __syncwarp();

            // ---- O += P V ----
#pragma unroll
            for (int ks = 0; ks < 8; ks++) {
                unsigned af[4];
                af[0] = __float_as_uint(Ps[r0l * QS + ks * 8 + tig]);
                af[1] = __float_as_uint(Ps[(r0l + 8) * QS + ks * 8 + tig]);
                af[2] = __float_as_uint(Ps[r0l * QS + ks * 8 + tig + 4]);
                af[3] = __float_as_uint(Ps[(r0l + 8) * QS + ks * 8 + tig + 4]);
#pragma unroll
                for (int nj = 0; nj < 8; nj++) {
                    int d0 = nj * 8 + g;
                    unsigned bf[2];
                    bf[0] = __float_as_uint(Vb[(ks * 8 + tig) * VSS + d0]);
                    bf[1] = __float_as_uint(Vb[(ks * 8 + tig + 4) * VSS + d0]);
                    mma_tf32(oacc[nj], af, bf);
                }
            }
            __syncwarp();
        }
    }

    // write O (divide by l, RN-round: operand of attnproj GEMM)
    {
        float li0 = 1.0f / l0, li1 = 1.0f / l1;
#pragma unroll
        for (int nj = 0; nj < 8; nj++) {
            int c = h * HD + nj * 8 + 2 * tig;
            *(float2*)&y[(size_t)(b * TDIM + row0) * CDIM + c] =
                make_float2(rtf(oacc[nj][0] * li0), rtf(oacc[nj][1] * li0));
            *(float2*)&y[(size_t)(b * TDIM + row1) * CDIM + c] =
                make_float2(rtf(oacc[nj][2] * li1), rtf(oacc[nj][3] * li1));
        }
    }

    // entropy: H_row = m + log(S) - W/S
    if (tig == 0) {
        hrow[warp * 16 + g]     = m0 + logf(l0) - w0 / l0;
        hrow[warp * 16 + g + 8] = m1 + logf(l1) - w1 / l1;
    }
    __syncthreads();
    if (tid == 0) {
        float tot = 0.f;
        for (int i = 0; i < 128; i++) tot += hrow[i];
        atomicAdd(&g_ent, tot);
    }
}

// ------------------------------------------------------------------
extern "C" void kernel_launch(void* const* d_in, const int* in_sizes, int n_in,
                              void* d_out, int out_size) {
    const float* x          = (const float*)d_in[0];
    const float* ln1_w      = (const float*)d_in[1];
    const float* ln1_b      = (const float*)d_in[2];
    const float* attn_w     = (const float*)d_in[3];
    const float* attn_b     = (const float*)d_in[4];
    const float* attnproj_w = (const float*)d_in[5];
    const float* attnproj_b = (const float*)d_in[6];
    const float* ln2_w      = (const float*)d_in[7];
    const float* ln2_b      = (const float*)d_in[8];
    const float* fc_w       = (const float*)d_in[9];
    const float* fc_b       = (const float*)d_in[10];
    const float* proj_w     = (const float*)d_in[11];
    const float* proj_b     = (const float*)d_in[12];
    float* out = (float*)d_out;

    float *p_h, *p_qkv, *p_y, *p_x1, *p_m, *p_wr;
    cudaGetSymbolAddress((void**)&p_h,   g_h);
    cudaGetSymbolAddress((void**)&p_qkv, g_qkv);
    cudaGetSymbolAddress((void**)&p_y,   g_y);
    cudaGetSymbolAddress((void**)&p_x1,  g_x1);
    cudaGetSymbolAddress((void**)&p_m,   g_m);
    cudaGetSymbolAddress((void**)&p_wr,  g_wr);

    static int gemm_smem = 6 * GBUF * 4;                            // 110592 B
    static int attn_smem = (2 * KB1 + 2 * VB1 + 128 * QS + 128) * 4; // ~107 KB
    cudaFuncSetAttribute(gemm_tc,
                         cudaFuncAttributeMaxDynamicSharedMemorySize, gemm_smem);
    cudaFuncSetAttribute(flash_attn_tc,
                         cudaFuncAttributeMaxDynamicSharedMemorySize, attn_smem);

    zero_ent_kernel<<<1, 1>>>();

    // RN-round weights to tf32 once per launch
    round4_kernel<<<3145728 / 1024, 256>>>(attn_w,     p_wr + WR_ATTN,  3145728);
    round4_kernel<<<1048576 / 1024, 256>>>(attnproj_w, p_wr + WR_APROJ, 1048576);
    round4_kernel<<<4194304 / 1024, 256>>>(fc_w,       p_wr + WR_FC,    4194304);
    round4_kernel<<<4194304 / 1024, 256>>>(proj_w,     p_wr + WR_PROJ,  4194304);

    // h = LN1(x)  (RN tf32)
    ln_kernel<<<BT, 256>>>(x, ln1_w, ln1_b, p_h);

    // qkv = h @ attn_w^T + attn_b
    gemm_tc<<<dim3(QKVC / 128, BT / 128), 256, gemm_smem>>>(
        p_h, p_wr + WR_ATTN, attn_b, nullptr, p_qkv, BT, QKVC, CDIM, 0, 1);

    // attention (+entropy)
    flash_attn_tc<<<dim3(TDIM / 128, BH), 256, attn_smem>>>(p_qkv, p_y);

    // x1 = x + y @ attnproj_w^T + attnproj_b
    gemm_tc<<<dim3(CDIM / 128, BT / 128), 256, gemm_smem>>>(
        p_y, p_wr + WR_APROJ, attnproj_b, x, p_x1, BT, CDIM, CDIM, 0, 0);

    // h = LN2(x1)  (RN tf32)
    ln_kernel<<<BT, 256>>>(p_x1, ln2_w, ln2_b, p_h);

    // m = gelu(h @ fc_w^T + fc_b)
    gemm_tc<<<dim3(FFC / 128, BT / 128), 256, gemm_smem>>>(
        p_h, p_wr + WR_FC, fc_b, nullptr, p_m, BT, FFC, CDIM, 1, 1);

    // out = x1 + m @ proj_w^T + proj_b
    gemm_tc<<<dim3(CDIM / 128, BT / 128), 256, gemm_smem>>>(
        p_m, p_wr + WR_PROJ, proj_b, p_x1, out, BT, CDIM, FFC, 0, 0);

    // entropy scalar
    finalize_kernel<<<1, 1>>>(out, out_size);
}